// round 7
// baseline (speedup 1.0000x reference)
#include <cuda_runtime.h>
#include <cuda_bf16.h>
#include <cstdint>

#define N_NODES   20000
#define N_EDGES   640000
#define BASIS     128
#define NUM_GAUSS 64
#define HIDDEN    256
#define NUM_GRAPHS 256

// ---------------- scratch (device globals) ----------------
__device__ float    g_dfeat[(size_t)N_EDGES * BASIS];  // dst-sorted d_feat
__device__ float    g_m[(size_t)N_EDGES * BASIS];      // dst-sorted messages
__device__ float    g_C[2][(size_t)N_NODES * BASIS];
__device__ float    g_Cc[(size_t)N_NODES * BASIS];
__device__ uint16_t g_Whi[BASIS * BASIS];              // fcW bf16 hi
__device__ uint16_t g_Wlo[BASIS * BASIS];              // fcW bf16 lo
__device__ int      g_perm[N_EDGES];                   // sorted pos -> orig edge
__device__ int      g_srcp[N_EDGES];                   // src in sorted order
__device__ int      g_cnt[N_NODES];
__device__ int      g_off[N_NODES + 1];
__device__ int      g_cur[N_NODES];

__device__ __forceinline__ float fast_tanh(float x) {
    float xc = fminf(fmaxf(x, -9.0f), 9.0f);
    float e  = __expf(2.0f * xc);
    return __fdividef(e - 1.0f, e + 1.0f);
}

__device__ __forceinline__ void split_bf16(float x, uint16_t& h, uint16_t& l) {
    __nv_bfloat16 hb = __float2bfloat16_rn(x);
    float hf = __bfloat162float(hb);
    __nv_bfloat16 lb = __float2bfloat16_rn(x - hf);
    h = __bfloat16_as_ushort(hb);
    l = __bfloat16_as_ushort(lb);
}

#define MMA_BF16(D, a0, a1, a2, a3, b0, b1)                                    \
    asm volatile("mma.sync.aligned.m16n8k16.row.col.f32.bf16.bf16.f32 "        \
                 "{%0,%1,%2,%3}, {%4,%5,%6,%7}, {%8,%9}, {%0,%1,%2,%3};"       \
                 : "+f"((D)[0]), "+f"((D)[1]), "+f"((D)[2]), "+f"((D)[3])      \
                 : "r"(a0), "r"(a1), "r"(a2), "r"(a3), "r"(b0), "r"(b1))

#define LDSM_X4(r0, r1, r2, r3, addr)                                          \
    asm volatile("ldmatrix.sync.aligned.m8n8.x4.shared.b16 {%0,%1,%2,%3}, [%4];" \
                 : "=r"(r0), "=r"(r1), "=r"(r2), "=r"(r3) : "r"(addr))

#define LDSM_X2(r0, r1, addr)                                                  \
    asm volatile("ldmatrix.sync.aligned.m8n8.x2.shared.b16 {%0,%1}, [%2];"     \
                 : "=r"(r0), "=r"(r1) : "r"(addr))

// ---------------- K0: zero output ----------------
__global__ void k_zero(float* __restrict__ out) {
    ((float4*)out)[threadIdx.x] = make_float4(0.f, 0.f, 0.f, 0.f);
}

// ---------------- K1: C0 = embed[Z] ----------------
__global__ __launch_bounds__(256) void k_init(const int* __restrict__ Z,
                                              const float* __restrict__ embed) {
    int idx = blockIdx.x * 256 + threadIdx.x;
    int v = idx >> 5, c4 = idx & 31;
    float4 val = ((const float4*)embed)[(size_t)Z[v] * 32 + c4];
    ((float4*)g_C[0])[idx] = val;
}

// ---------------- sort-by-dst pipeline ----------------
__global__ __launch_bounds__(256) void k_clear() {
    int i = blockIdx.x * 256 + threadIdx.x;
    if (i < N_NODES) g_cnt[i] = 0;
}

__global__ __launch_bounds__(256) void k_hist(const int* __restrict__ edge_index) {
    int e = blockIdx.x * 256 + threadIdx.x;
    if (e < N_EDGES) atomicAdd(&g_cnt[edge_index[N_EDGES + e]], 1);
}

__global__ __launch_bounds__(1024) void k_scan() {
    __shared__ int sdata[1024];
    int t = threadIdx.x;
    const int PER = 20;                      // 1024*20 >= 20000
    int base = t * PER;
    int v[PER]; int s = 0;
#pragma unroll
    for (int j = 0; j < PER; j++) {
        int i = base + j;
        v[j] = (i < N_NODES) ? g_cnt[i] : 0;
        s += v[j];
    }
    sdata[t] = s;
    __syncthreads();
    for (int off = 1; off < 1024; off <<= 1) {
        int y = (t >= off) ? sdata[t - off] : 0;
        __syncthreads();
        sdata[t] += y;
        __syncthreads();
    }
    int run = sdata[t] - s;                  // exclusive prefix
#pragma unroll
    for (int j = 0; j < PER; j++) {
        int i = base + j;
        if (i < N_NODES) { g_off[i] = run; g_cur[i] = run; run += v[j]; }
    }
    if (t == 1023) g_off[N_NODES] = run;
}

__global__ __launch_bounds__(256) void k_scatter(const int* __restrict__ edge_index) {
    int e = blockIdx.x * 256 + threadIdx.x;
    if (e < N_EDGES) {
        int dst = edge_index[N_EDGES + e];
        int pos = atomicAdd(&g_cur[dst], 1);
        g_perm[pos] = e;
        g_srcp[pos] = edge_index[e];
    }
}

// ---------------- precompute fcW bf16 split (once per launch) ----------------
__global__ __launch_bounds__(256) void k_wsplit(const float* __restrict__ fcW) {
    for (int i = blockIdx.x * 256 + threadIdx.x; i < BASIS * BASIS; i += gridDim.x * 256) {
        uint16_t h, l;
        split_bf16(fcW[i], h, l);
        g_Whi[i] = h; g_Wlo[i] = l;
    }
}

// ---------------- K2: d_feat (dst-sorted) = edge_attr[perm] @ dfW.T + dfb ------
__global__ __launch_bounds__(256) void k_dfeat(const float* __restrict__ edge_attr,
                                               const float* __restrict__ dfW,
                                               const float* __restrict__ dfb) {
    extern __shared__ float sm[];
    float* sW = sm;                  // [128][64]
    float* sA = sm + 128 * 64;       // [64][68]
    float* sB = sA + 64 * 68;        // [128]
    int*   sPerm = (int*)(sB + 128); // [64]
    int t = threadIdx.x;
    int e0 = blockIdx.x * 64;

    if (t < 64) sPerm[t] = g_perm[e0 + t];
    __syncthreads();

    for (int i = t; i < 2048; i += 256)
        ((float4*)sW)[i] = ((const float4*)dfW)[i];
    if (t < 128) sB[t] = dfb[t];
    for (int i = t; i < 64 * 16; i += 256) {
        int e = i >> 4, g4 = i & 15;
        float4 v = ((const float4*)edge_attr)[(size_t)sPerm[e] * 16 + g4];
        *(float4*)&sA[e * 68 + g4 * 4] = v;
    }
    __syncthreads();

    int tx = t & 7, ty = t >> 3;
    float acc[8][4];
#pragma unroll
    for (int ii = 0; ii < 8; ii++)
#pragma unroll
        for (int jj = 0; jj < 4; jj++) acc[ii][jj] = 0.f;

#pragma unroll 4
    for (int k = 0; k < 64; k += 4) {
        float4 av[8], wv[4];
#pragma unroll
        for (int ii = 0; ii < 8; ii++) av[ii] = *(float4*)&sA[(tx + 8 * ii) * 68 + k];
#pragma unroll
        for (int jj = 0; jj < 4; jj++) wv[jj] = *(float4*)&sW[(ty * 4 + jj) * 64 + k];
#pragma unroll
        for (int ii = 0; ii < 8; ii++)
#pragma unroll
            for (int jj = 0; jj < 4; jj++) {
                acc[ii][jj] = fmaf(av[ii].x, wv[jj].x, acc[ii][jj]);
                acc[ii][jj] = fmaf(av[ii].y, wv[jj].y, acc[ii][jj]);
                acc[ii][jj] = fmaf(av[ii].z, wv[jj].z, acc[ii][jj]);
                acc[ii][jj] = fmaf(av[ii].w, wv[jj].w, acc[ii][jj]);
            }
    }
    float4 bb = *(float4*)&sB[ty * 4];
#pragma unroll
    for (int ii = 0; ii < 8; ii++) {
        float4 o = make_float4(acc[ii][0] + bb.x, acc[ii][1] + bb.y,
                               acc[ii][2] + bb.z, acc[ii][3] + bb.w);
        ((float4*)g_dfeat)[(size_t)(e0 + tx + 8 * ii) * 32 + ty] = o;
    }
}

// ---------------- K3: Cc = C@cfW.T + cfb (no copy) ----------------
__global__ __launch_bounds__(256) void k_node(const float* __restrict__ cfW,
                                              const float* __restrict__ cfb,
                                              int sb) {
    extern __shared__ float sm[];
    float* sW = sm;                  // [128][128]
    float* sC = sm + 16384;          // [32][132]
    float* sBb = sC + 32 * 132;      // [128]
    const float* C = g_C[sb];
    int t = threadIdx.x, n0 = blockIdx.x * 32;

    for (int i = t; i < 4096; i += 256)
        ((float4*)sW)[i] = ((const float4*)cfW)[i];
    if (t < 128) sBb[t] = cfb[t];
    for (int i = t; i < 32 * 32; i += 256) {
        int n = i >> 5, c4 = i & 31;
        *(float4*)&sC[n * 132 + c4 * 4] = ((const float4*)C)[(size_t)(n0 + n) * 32 + c4];
    }
    __syncthreads();

    int tx = t & 7, ty = t >> 3;
    float acc[4][4];
#pragma unroll
    for (int ii = 0; ii < 4; ii++)
#pragma unroll
        for (int jj = 0; jj < 4; jj++) acc[ii][jj] = 0.f;

#pragma unroll 4
    for (int k = 0; k < 128; k += 4) {
        float4 cv[4], wv[4];
#pragma unroll
        for (int ii = 0; ii < 4; ii++) cv[ii] = *(float4*)&sC[(tx + 8 * ii) * 132 + k];
#pragma unroll
        for (int jj = 0; jj < 4; jj++) wv[jj] = *(float4*)&sW[(ty * 4 + jj) * 128 + k];
#pragma unroll
        for (int ii = 0; ii < 4; ii++)
#pragma unroll
            for (int jj = 0; jj < 4; jj++) {
                acc[ii][jj] = fmaf(cv[ii].x, wv[jj].x, acc[ii][jj]);
                acc[ii][jj] = fmaf(cv[ii].y, wv[jj].y, acc[ii][jj]);
                acc[ii][jj] = fmaf(cv[ii].z, wv[jj].z, acc[ii][jj]);
                acc[ii][jj] = fmaf(cv[ii].w, wv[jj].w, acc[ii][jj]);
            }
    }
    float4 bb = *(float4*)&sBb[ty * 4];
#pragma unroll
    for (int ii = 0; ii < 4; ii++) {
        float4 o = make_float4(acc[ii][0] + bb.x, acc[ii][1] + bb.y,
                               acc[ii][2] + bb.z, acc[ii][3] + bb.w);
        ((float4*)g_Cc)[(size_t)(n0 + tx + 8 * ii) * 32 + ty] = o;
    }
}

// ---------------- K4 (hot): m = tanh((Cc[srcp]*d_feat)@fcW.T) -> g_m ------------
// TE=64 edges/block, 128 threads (4 warps), 2 blocks/SM. No atomics.
#define TE  64
#define PB  136   // bf16 row stride
#define POS 132   // f32 staging stride
__global__ __launch_bounds__(128) void k_edge(int sb) {
    extern __shared__ char smraw[];
    uint16_t* sWhi = (uint16_t*)smraw;               // [128][136]
    uint16_t* sWlo = sWhi + 128 * PB;                // [128][136]
    uint16_t* sPhi = sWlo + 128 * PB;                // [64][136]
    uint16_t* sPlo = sPhi + TE * PB;                 // [64][136]
    int*      sSrc = (int*)(sPlo + TE * PB);         // [64]
    float*    sOut = (float*)sPhi;                   // [64][132], aliases P
    int t = threadIdx.x, e0 = blockIdx.x * TE;

    // ---- phase 1: stage pre-split W; load src ----
    for (int i = t; i < 2048; i += 128) {            // uint4 = 8 bf16
        int n = i >> 4, k8 = i & 15;
        *(uint4*)&sWhi[n * PB + k8 * 8] = ((const uint4*)g_Whi)[i];
        *(uint4*)&sWlo[n * PB + k8 * 8] = ((const uint4*)g_Wlo)[i];
    }
    if (t < TE) sSrc[t] = g_srcp[e0 + t];
    __syncthreads();

    // ---- phase 2: build & split P = Cc[src] * d_feat ----
    for (int i = t; i < TE * 32; i += 128) {
        int e = i >> 5, c4 = i & 31;
        float4 d = ((const float4*)g_dfeat)[(size_t)(e0 + e) * 32 + c4];
        float4 c = ((const float4*)g_Cc)[(size_t)sSrc[e] * 32 + c4];
        float4 p = make_float4(d.x * c.x, d.y * c.y, d.z * c.z, d.w * c.w);
        uint16_t h0, h1, h2, h3, l0, l1, l2, l3;
        split_bf16(p.x, h0, l0); split_bf16(p.y, h1, l1);
        split_bf16(p.z, h2, l2); split_bf16(p.w, h3, l3);
        *(uint2*)&sPhi[e * PB + c4 * 4] =
            make_uint2((uint32_t)h0 | ((uint32_t)h1 << 16), (uint32_t)h2 | ((uint32_t)h3 << 16));
        *(uint2*)&sPlo[e * PB + c4 * 4] =
            make_uint2((uint32_t)l0 | ((uint32_t)l1 << 16), (uint32_t)l2 | ((uint32_t)l3 << 16));
    }
    __syncthreads();

    // ---- phase 3: bf16-split GEMM  D[64x128] = P @ W^T ----
    const int lane = t & 31, wid = t >> 5;
    const int mbase = (wid >> 1) * 32;               // {0,32}
    const int nbase = (wid & 1) * 64;                // {0,64}
    const int aoff = (mbase + (lane & 15)) * PB + ((lane & 16) ? 8 : 0);
    const int boff = (nbase + (lane & 7)) * PB + ((lane & 8) ? 8 : 0);
    const uint32_t sPhiA = (uint32_t)__cvta_generic_to_shared(sPhi);
    const uint32_t sPloA = (uint32_t)__cvta_generic_to_shared(sPlo);
    const uint32_t sWhiA = (uint32_t)__cvta_generic_to_shared(sWhi);
    const uint32_t sWloA = (uint32_t)__cvta_generic_to_shared(sWlo);

    float acc[64];
#pragma unroll
    for (int i = 0; i < 64; i++) acc[i] = 0.f;

#pragma unroll
    for (int kt = 0; kt < 8; kt++) {
        uint32_t ahi[2][4], alo[2][4];
#pragma unroll
        for (int mt = 0; mt < 2; mt++) {
            uint32_t off = (uint32_t)(aoff + mt * 16 * PB + kt * 16) * 2;
            LDSM_X4(ahi[mt][0], ahi[mt][1], ahi[mt][2], ahi[mt][3], sPhiA + off);
            LDSM_X4(alo[mt][0], alo[mt][1], alo[mt][2], alo[mt][3], sPloA + off);
        }
#pragma unroll
        for (int nt = 0; nt < 8; nt++) {
            uint32_t off = (uint32_t)(boff + nt * 8 * PB + kt * 16) * 2;
            uint32_t bh0, bh1, bl0, bl1;
            LDSM_X2(bh0, bh1, sWhiA + off);
            LDSM_X2(bl0, bl1, sWloA + off);
#pragma unroll
            for (int mt = 0; mt < 2; mt++) {
                float* D = acc + (mt * 8 + nt) * 4;
                MMA_BF16(D, ahi[mt][0], ahi[mt][1], ahi[mt][2], ahi[mt][3], bh0, bh1);
                MMA_BF16(D, ahi[mt][0], ahi[mt][1], ahi[mt][2], ahi[mt][3], bl0, bl1);
                MMA_BF16(D, alo[mt][0], alo[mt][1], alo[mt][2], alo[mt][3], bh0, bh1);
            }
        }
    }
    __syncthreads();                                 // P reads done

    // ---- phase 4: tanh -> staging ----
    const int grp = lane >> 2, t4 = lane & 3;
#pragma unroll
    for (int mt = 0; mt < 2; mt++)
#pragma unroll
        for (int nt = 0; nt < 8; nt++) {
            int m = mbase + mt * 16 + grp;
            int n = nbase + nt * 8 + 2 * t4;
            const float* D = acc + (mt * 8 + nt) * 4;
            *(float2*)&sOut[m * POS + n] = make_float2(fast_tanh(D[0]), fast_tanh(D[1]));
            *(float2*)&sOut[(m + 8) * POS + n] = make_float2(fast_tanh(D[2]), fast_tanh(D[3]));
        }
    __syncthreads();

    // ---- phase 5: coalesced store to g_m (dst-sorted) ----
    for (int i = t; i < TE * 32; i += 128) {
        int e = i >> 5, c4 = i & 31;
        ((float4*)g_m)[(size_t)(e0 + e) * 32 + c4] = *(float4*)&sOut[e * POS + c4 * 4];
    }
}

// ---------------- K4b: segment-sum aggregation, C2 = C + sum(m[seg]) ------------
__global__ __launch_bounds__(256) void k_agg(int sb) {
    const float* C = g_C[sb];
    float* C2 = g_C[sb ^ 1];
    int t = threadIdx.x;
    int n = blockIdx.x * 8 + (t >> 5);
    int lane = t & 31;
    int s0 = g_off[n], s1 = g_off[n + 1];
    float4 a = make_float4(0.f, 0.f, 0.f, 0.f);
    int r = s0;
    for (; r + 4 <= s1; r += 4) {
        float4 v0 = ((const float4*)g_m)[(size_t)(r + 0) * 32 + lane];
        float4 v1 = ((const float4*)g_m)[(size_t)(r + 1) * 32 + lane];
        float4 v2 = ((const float4*)g_m)[(size_t)(r + 2) * 32 + lane];
        float4 v3 = ((const float4*)g_m)[(size_t)(r + 3) * 32 + lane];
        a.x += v0.x + v1.x + v2.x + v3.x;
        a.y += v0.y + v1.y + v2.y + v3.y;
        a.z += v0.z + v1.z + v2.z + v3.z;
        a.w += v0.w + v1.w + v2.w + v3.w;
    }
    for (; r < s1; r++) {
        float4 v = ((const float4*)g_m)[(size_t)r * 32 + lane];
        a.x += v.x; a.y += v.y; a.z += v.z; a.w += v.w;
    }
    float4 c = ((const float4*)C)[(size_t)n * 32 + lane];
    ((float4*)C2)[(size_t)n * 32 + lane] =
        make_float4(c.x + a.x, c.y + a.y, c.z + a.z, c.w + a.w);
}

// ---------------- K5: readout + pool ----------------
__global__ __launch_bounds__(256) void k_readout(const float* __restrict__ r1W,
                                                 const float* __restrict__ r1b,
                                                 const float* __restrict__ r2W,
                                                 const float* __restrict__ r2b,
                                                 const int* __restrict__ batch,
                                                 float* __restrict__ out, int sb) {
    extern __shared__ float sm[];
    float* sW1 = sm;                   // [256][128]
    float* sC  = sW1 + 32768;          // [32][132]
    float* sW2 = sC + 32 * 132;        // [4][256]
    float* sB1 = sW2 + 1024;           // [256]
    float* sAcc = sB1 + 256;           // [32][4]
    int*   sBat = (int*)(sAcc + 128);  // [32]
    const float* C = g_C[sb];
    int t = threadIdx.x, n0 = blockIdx.x * 32;

    for (int i = t; i < 8192; i += 256)
        ((float4*)sW1)[i] = ((const float4*)r1W)[i];
    if (t < 256) ((float4*)sW2)[t] = ((const float4*)r2W)[t];
    sB1[t] = r1b[t];
    if (t < 128) sAcc[t] = 0.f;
    if (t < 32)  sBat[t] = batch[n0 + t];
    for (int i = t; i < 32 * 32; i += 256) {
        int n = i >> 5, c4 = i & 31;
        *(float4*)&sC[n * 132 + c4 * 4] = ((const float4*)C)[(size_t)(n0 + n) * 32 + c4];
    }
    __syncthreads();

    int tx = t & 7, ty = t >> 3;
    float acc[4][8];
#pragma unroll
    for (int ii = 0; ii < 4; ii++)
#pragma unroll
        for (int jj = 0; jj < 8; jj++) acc[ii][jj] = 0.f;

#pragma unroll 2
    for (int c = 0; c < 128; c += 4) {
        float4 cv[4], wv[8];
#pragma unroll
        for (int ii = 0; ii < 4; ii++) cv[ii] = *(float4*)&sC[(tx + 8 * ii) * 132 + c];
#pragma unroll
        for (int jj = 0; jj < 8; jj++) wv[jj] = *(float4*)&sW1[(ty * 8 + jj) * 128 + c];
#pragma unroll
        for (int ii = 0; ii < 4; ii++)
#pragma unroll
            for (int jj = 0; jj < 8; jj++) {
                acc[ii][jj] = fmaf(cv[ii].x, wv[jj].x, acc[ii][jj]);
                acc[ii][jj] = fmaf(cv[ii].y, wv[jj].y, acc[ii][jj]);
                acc[ii][jj] = fmaf(cv[ii].z, wv[jj].z, acc[ii][jj]);
                acc[ii][jj] = fmaf(cv[ii].w, wv[jj].w, acc[ii][jj]);
            }
    }
    float po[4][4];
#pragma unroll
    for (int ii = 0; ii < 4; ii++)
#pragma unroll
        for (int o = 0; o < 4; o++) po[ii][o] = (ty == 0) ? r2b[o] : 0.f;
#pragma unroll
    for (int ii = 0; ii < 4; ii++)
#pragma unroll
        for (int jj = 0; jj < 8; jj++) {
            float h = fast_tanh(acc[ii][jj] + sB1[ty * 8 + jj]);
#pragma unroll
            for (int o = 0; o < 4; o++)
                po[ii][o] = fmaf(h, sW2[o * 256 + ty * 8 + jj], po[ii][o]);
        }
#pragma unroll
    for (int ii = 0; ii < 4; ii++)
#pragma unroll
        for (int o = 0; o < 4; o++)
            atomicAdd(&sAcc[(tx + 8 * ii) * 4 + o], po[ii][o]);
    __syncthreads();
    if (t < 128) {
        int n = t >> 2, o = t & 3;
        atomicAdd(&out[(size_t)sBat[n] * 4 + o], sAcc[t]);
    }
}

// ---------------- launch ----------------
extern "C" void kernel_launch(void* const* d_in, const int* in_sizes, int n_in,
                              void* d_out, int out_size) {
    const int*   Z         = (const int*)d_in[0];
    const int*   edge_index= (const int*)d_in[1];
    const float* edge_attr = (const float*)d_in[2];
    const int*   batch     = (const int*)d_in[3];
    const float* embed     = (const float*)d_in[4];
    const float* cfW       = (const float*)d_in[5];
    const float* cfb       = (const float*)d_in[6];
    const float* dfW       = (const float*)d_in[7];
    const float* dfb       = (const float*)d_in[8];
    const float* fcW       = (const float*)d_in[9];
    const float* r1W       = (const float*)d_in[10];
    const float* r1b       = (const float*)d_in[11];
    const float* r2W       = (const float*)d_in[12];
    const float* r2b       = (const float*)d_in[13];
    float* out = (float*)d_out;

    const int smK2 = (128 * 64 + 64 * 68 + 128) * 4 + 64 * 4;             // ~51 KB
    const int smK3 = (16384 + 32 * 132 + 128) * 4;                        // ~83 KB
    const int smK4 = (2 * 128 * PB + 2 * TE * PB) * 2 + TE * 4;           // ~105 KB
    const int smK5 = (32768 + 32 * 132 + 1024 + 256 + 128) * 4 + 32 * 4;  // ~154 KB

    cudaFuncSetAttribute(k_dfeat,   cudaFuncAttributeMaxDynamicSharedMemorySize, smK2);
    cudaFuncSetAttribute(k_node,    cudaFuncAttributeMaxDynamicSharedMemorySize, smK3);
    cudaFuncSetAttribute(k_edge,    cudaFuncAttributeMaxDynamicSharedMemorySize, smK4);
    cudaFuncSetAttribute(k_readout, cudaFuncAttributeMaxDynamicSharedMemorySize, smK5);

    k_zero<<<1, 256>>>(out);
    k_init<<<(N_NODES * 32) / 256, 256>>>(Z, embed);

    // one-time (per launch) edge sort by dst + W split
    k_clear<<<(N_NODES + 255) / 256, 256>>>();
    k_hist<<<(N_EDGES + 255) / 256, 256>>>(edge_index);
    k_scan<<<1, 1024>>>();
    k_scatter<<<(N_EDGES + 255) / 256, 256>>>(edge_index);
    k_wsplit<<<64, 256>>>(fcW);

    k_dfeat<<<N_EDGES / 64, 256, smK2>>>(edge_attr, dfW, dfb);

    int sb = 0;
    for (int it = 0; it < 3; it++) {
        k_node<<<N_NODES / 32, 256, smK3>>>(cfW, cfb, sb);
        k_edge<<<N_EDGES / TE, 128, smK4>>>(sb);
        k_agg<<<N_NODES / 8, 256>>>(sb);
        sb ^= 1;
    }
    k_readout<<<N_NODES / 32, 256, smK5>>>(r1W, r1b, r2W, r2b, batch, out, sb);
}

// round 9
// speedup vs baseline: 1.2663x; 1.2663x over previous
#include <cuda_runtime.h>
#include <cuda_bf16.h>
#include <cstdint>

#define N_NODES   20000
#define N_EDGES   640000
#define BASIS     128
#define NUM_GAUSS 64
#define HIDDEN    256
#define NUM_GRAPHS 256

// ---------------- scratch (device globals) ----------------
__device__ float    g_dfeat[(size_t)N_EDGES * BASIS];  // dst-sorted d_feat
__device__ float    g_C[2][(size_t)N_NODES * BASIS];   // ping-pong node states
__device__ float    g_Cc[(size_t)N_NODES * BASIS];     // per-iter node transform
__device__ uint16_t g_Whi[BASIS * BASIS];              // fcW bf16 hi
__device__ uint16_t g_Wlo[BASIS * BASIS];              // fcW bf16 lo
__device__ int      g_perm[N_EDGES];                   // sorted pos -> orig edge
__device__ int      g_srcp[N_EDGES];                   // src in sorted order
__device__ int      g_dstp[N_EDGES];                   // dst in sorted order
__device__ int      g_cnt[N_NODES];
__device__ int      g_off[N_NODES + 1];
__device__ int      g_cur[N_NODES];

__device__ __forceinline__ float fast_tanh(float x) {
    float xc = fminf(fmaxf(x, -9.0f), 9.0f);
    float e  = __expf(2.0f * xc);
    return __fdividef(e - 1.0f, e + 1.0f);
}

__device__ __forceinline__ void split_bf16(float x, uint16_t& h, uint16_t& l) {
    __nv_bfloat16 hb = __float2bfloat16_rn(x);
    float hf = __bfloat162float(hb);
    __nv_bfloat16 lb = __float2bfloat16_rn(x - hf);
    h = __bfloat16_as_ushort(hb);
    l = __bfloat16_as_ushort(lb);
}

#define MMA_BF16(D, a0, a1, a2, a3, b0, b1)                                    \
    asm volatile("mma.sync.aligned.m16n8k16.row.col.f32.bf16.bf16.f32 "        \
                 "{%0,%1,%2,%3}, {%4,%5,%6,%7}, {%8,%9}, {%0,%1,%2,%3};"       \
                 : "+f"((D)[0]), "+f"((D)[1]), "+f"((D)[2]), "+f"((D)[3])      \
                 : "r"(a0), "r"(a1), "r"(a2), "r"(a3), "r"(b0), "r"(b1))

#define LDSM_X4(r0, r1, r2, r3, addr)                                          \
    asm volatile("ldmatrix.sync.aligned.m8n8.x4.shared.b16 {%0,%1,%2,%3}, [%4];" \
                 : "=r"(r0), "=r"(r1), "=r"(r2), "=r"(r3) : "r"(addr))

#define LDSM_X2(r0, r1, addr)                                                  \
    asm volatile("ldmatrix.sync.aligned.m8n8.x2.shared.b16 {%0,%1}, [%2];"     \
                 : "=r"(r0), "=r"(r1) : "r"(addr))

// ---------------- K0: zero output ----------------
__global__ void k_zero(float* __restrict__ out) {
    ((float4*)out)[threadIdx.x] = make_float4(0.f, 0.f, 0.f, 0.f);
}

// ---------------- K1: C0 = embed[Z] ----------------
__global__ __launch_bounds__(256) void k_init(const int* __restrict__ Z,
                                              const float* __restrict__ embed) {
    int idx = blockIdx.x * 256 + threadIdx.x;
    int v = idx >> 5, c4 = idx & 31;
    float4 val = ((const float4*)embed)[(size_t)Z[v] * 32 + c4];
    ((float4*)g_C[0])[idx] = val;
}

// ---------------- sort-by-dst pipeline (one-time, ~40us) ----------------
__global__ __launch_bounds__(256) void k_clear() {
    int i = blockIdx.x * 256 + threadIdx.x;
    if (i < N_NODES) g_cnt[i] = 0;
}

__global__ __launch_bounds__(256) void k_hist(const int* __restrict__ edge_index) {
    int e = blockIdx.x * 256 + threadIdx.x;
    if (e < N_EDGES) atomicAdd(&g_cnt[edge_index[N_EDGES + e]], 1);
}

__global__ __launch_bounds__(1024) void k_scan() {
    __shared__ int sdata[1024];
    int t = threadIdx.x;
    const int PER = 20;
    int base = t * PER;
    int v[PER]; int s = 0;
#pragma unroll
    for (int j = 0; j < PER; j++) {
        int i = base + j;
        v[j] = (i < N_NODES) ? g_cnt[i] : 0;
        s += v[j];
    }
    sdata[t] = s;
    __syncthreads();
    for (int off = 1; off < 1024; off <<= 1) {
        int y = (t >= off) ? sdata[t - off] : 0;
        __syncthreads();
        sdata[t] += y;
        __syncthreads();
    }
    int run = sdata[t] - s;
#pragma unroll
    for (int j = 0; j < PER; j++) {
        int i = base + j;
        if (i < N_NODES) { g_off[i] = run; g_cur[i] = run; run += v[j]; }
    }
    if (t == 1023) g_off[N_NODES] = run;
}

__global__ __launch_bounds__(256) void k_scatter(const int* __restrict__ edge_index) {
    int e = blockIdx.x * 256 + threadIdx.x;
    if (e < N_EDGES) {
        int dst = edge_index[N_EDGES + e];
        int pos = atomicAdd(&g_cur[dst], 1);
        g_perm[pos] = e;
        g_srcp[pos] = edge_index[e];
        g_dstp[pos] = dst;
    }
}

// ---------------- precompute fcW bf16 split ----------------
__global__ __launch_bounds__(256) void k_wsplit(const float* __restrict__ fcW) {
    for (int i = blockIdx.x * 256 + threadIdx.x; i < BASIS * BASIS; i += gridDim.x * 256) {
        uint16_t h, l;
        split_bf16(fcW[i], h, l);
        g_Whi[i] = h; g_Wlo[i] = l;
    }
}

// ---------------- K2: d_feat (dst-sorted) = edge_attr[perm] @ dfW.T + dfb ------
__global__ __launch_bounds__(256) void k_dfeat(const float* __restrict__ edge_attr,
                                               const float* __restrict__ dfW,
                                               const float* __restrict__ dfb) {
    extern __shared__ float sm[];
    float* sW = sm;                  // [128][64]
    float* sA = sm + 128 * 64;       // [64][68]
    float* sB = sA + 64 * 68;        // [128]
    int*   sPerm = (int*)(sB + 128); // [64]
    int t = threadIdx.x;
    int e0 = blockIdx.x * 64;

    if (t < 64) sPerm[t] = g_perm[e0 + t];
    __syncthreads();

    for (int i = t; i < 2048; i += 256)
        ((float4*)sW)[i] = ((const float4*)dfW)[i];
    if (t < 128) sB[t] = dfb[t];
    for (int i = t; i < 64 * 16; i += 256) {
        int e = i >> 4, g4 = i & 15;
        float4 v = ((const float4*)edge_attr)[(size_t)sPerm[e] * 16 + g4];
        *(float4*)&sA[e * 68 + g4 * 4] = v;
    }
    __syncthreads();

    int tx = t & 7, ty = t >> 3;
    float acc[8][4];
#pragma unroll
    for (int ii = 0; ii < 8; ii++)
#pragma unroll
        for (int jj = 0; jj < 4; jj++) acc[ii][jj] = 0.f;

#pragma unroll 4
    for (int k = 0; k < 64; k += 4) {
        float4 av[8], wv[4];
#pragma unroll
        for (int ii = 0; ii < 8; ii++) av[ii] = *(float4*)&sA[(tx + 8 * ii) * 68 + k];
#pragma unroll
        for (int jj = 0; jj < 4; jj++) wv[jj] = *(float4*)&sW[(ty * 4 + jj) * 64 + k];
#pragma unroll
        for (int ii = 0; ii < 8; ii++)
#pragma unroll
            for (int jj = 0; jj < 4; jj++) {
                acc[ii][jj] = fmaf(av[ii].x, wv[jj].x, acc[ii][jj]);
                acc[ii][jj] = fmaf(av[ii].y, wv[jj].y, acc[ii][jj]);
                acc[ii][jj] = fmaf(av[ii].z, wv[jj].z, acc[ii][jj]);
                acc[ii][jj] = fmaf(av[ii].w, wv[jj].w, acc[ii][jj]);
            }
    }
    float4 bb = *(float4*)&sB[ty * 4];
#pragma unroll
    for (int ii = 0; ii < 8; ii++) {
        float4 o = make_float4(acc[ii][0] + bb.x, acc[ii][1] + bb.y,
                               acc[ii][2] + bb.z, acc[ii][3] + bb.w);
        ((float4*)g_dfeat)[(size_t)(e0 + tx + 8 * ii) * 32 + ty] = o;
    }
}

// ---------------- K3: Cc = C@cfW.T + cfb ; C2 = C (scatter base) ----------------
__global__ __launch_bounds__(256) void k_node(const float* __restrict__ cfW,
                                              const float* __restrict__ cfb,
                                              int sb) {
    extern __shared__ float sm[];
    float* sW = sm;                  // [128][128]
    float* sC = sm + 16384;          // [32][132]
    float* sBb = sC + 32 * 132;      // [128]
    const float* C = g_C[sb];
    float* C2 = g_C[sb ^ 1];
    int t = threadIdx.x, n0 = blockIdx.x * 32;

    for (int i = t; i < 4096; i += 256)
        ((float4*)sW)[i] = ((const float4*)cfW)[i];
    if (t < 128) sBb[t] = cfb[t];
    for (int i = t; i < 32 * 32; i += 256) {
        int n = i >> 5, c4 = i & 31;
        *(float4*)&sC[n * 132 + c4 * 4] = ((const float4*)C)[(size_t)(n0 + n) * 32 + c4];
    }
    __syncthreads();

    int tx = t & 7, ty = t >> 3;
    float acc[4][4];
#pragma unroll
    for (int ii = 0; ii < 4; ii++)
#pragma unroll
        for (int jj = 0; jj < 4; jj++) acc[ii][jj] = 0.f;

#pragma unroll 4
    for (int k = 0; k < 128; k += 4) {
        float4 cv[4], wv[4];
#pragma unroll
        for (int ii = 0; ii < 4; ii++) cv[ii] = *(float4*)&sC[(tx + 8 * ii) * 132 + k];
#pragma unroll
        for (int jj = 0; jj < 4; jj++) wv[jj] = *(float4*)&sW[(ty * 4 + jj) * 128 + k];
#pragma unroll
        for (int ii = 0; ii < 4; ii++)
#pragma unroll
            for (int jj = 0; jj < 4; jj++) {
                acc[ii][jj] = fmaf(cv[ii].x, wv[jj].x, acc[ii][jj]);
                acc[ii][jj] = fmaf(cv[ii].y, wv[jj].y, acc[ii][jj]);
                acc[ii][jj] = fmaf(cv[ii].z, wv[jj].z, acc[ii][jj]);
                acc[ii][jj] = fmaf(cv[ii].w, wv[jj].w, acc[ii][jj]);
            }
    }
    float4 bb = *(float4*)&sBb[ty * 4];
#pragma unroll
    for (int ii = 0; ii < 4; ii++) {
        float4 o = make_float4(acc[ii][0] + bb.x, acc[ii][1] + bb.y,
                               acc[ii][2] + bb.z, acc[ii][3] + bb.w);
        ((float4*)g_Cc)[(size_t)(n0 + tx + 8 * ii) * 32 + ty] = o;
    }
    for (int i = t; i < 32 * 32; i += 256) {
        int n = i >> 5, c4 = i & 31;
        ((float4*)C2)[(size_t)(n0 + n) * 32 + c4] = *(float4*)&sC[n * 132 + c4 * 4];
    }
}

// ---------------- K4 (hot): m = tanh((Cc[srcp]*d_feat)@fcW.T); C2[dst] += m -----
// dst-sorted edges -> block-local segment pre-aggregation before global atomics.
// TE=64 edges/block, 128 threads, ~102.5 KB smem -> 2 blocks/SM.
#define TE  64
#define PB  136   // bf16 row stride
#define POS 132   // f32 staging stride
__global__ __launch_bounds__(128) void k_edge(int db) {
    extern __shared__ char smraw[];
    uint16_t* sWhi = (uint16_t*)smraw;               // [128][136]
    uint16_t* sWlo = sWhi + 128 * PB;                // [128][136]
    uint16_t* sPhi = sWlo + 128 * PB;                // [64][136]
    uint16_t* sPlo = sPhi + TE * PB;                 // [64][136]
    int*      sSrc = (int*)(sPlo + TE * PB);         // [64]
    int*      sDst = sSrc + TE;                      // [64]
    float*    sOut = (float*)sPhi;                   // [64][132], aliases P
    float* C2 = g_C[db];
    int t = threadIdx.x, e0 = blockIdx.x * TE;

    // ---- phase 1: stage pre-split W; load src/dst ----
    for (int i = t; i < 2048; i += 128) {            // uint4 = 8 bf16
        int n = i >> 4, k8 = i & 15;
        *(uint4*)&sWhi[n * PB + k8 * 8] = ((const uint4*)g_Whi)[i];
        *(uint4*)&sWlo[n * PB + k8 * 8] = ((const uint4*)g_Wlo)[i];
    }
    if (t < TE)          sSrc[t]      = g_srcp[e0 + t];
    else if (t < 2 * TE) sDst[t - TE] = g_dstp[e0 + (t - TE)];
    __syncthreads();

    // ---- phase 2: build & split P = Cc[src] * d_feat ----
    for (int i = t; i < TE * 32; i += 128) {
        int e = i >> 5, c4 = i & 31;
        float4 d = ((const float4*)g_dfeat)[(size_t)(e0 + e) * 32 + c4];
        float4 c = ((const float4*)g_Cc)[(size_t)sSrc[e] * 32 + c4];
        float4 p = make_float4(d.x * c.x, d.y * c.y, d.z * c.z, d.w * c.w);
        uint16_t h0, h1, h2, h3, l0, l1, l2, l3;
        split_bf16(p.x, h0, l0); split_bf16(p.y, h1, l1);
        split_bf16(p.z, h2, l2); split_bf16(p.w, h3, l3);
        *(uint2*)&sPhi[e * PB + c4 * 4] =
            make_uint2((uint32_t)h0 | ((uint32_t)h1 << 16), (uint32_t)h2 | ((uint32_t)h3 << 16));
        *(uint2*)&sPlo[e * PB + c4 * 4] =
            make_uint2((uint32_t)l0 | ((uint32_t)l1 << 16), (uint32_t)l2 | ((uint32_t)l3 << 16));
    }
    __syncthreads();

    // ---- phase 3: bf16-split GEMM  D[64x128] = P @ W^T ----
    const int lane = t & 31, wid = t >> 5;
    const int mbase = (wid >> 1) * 32;               // {0,32}
    const int nbase = (wid & 1) * 64;                // {0,64}
    const int aoff = (mbase + (lane & 15)) * PB + ((lane & 16) ? 8 : 0);
    const int boff = (nbase + (lane & 7)) * PB + ((lane & 8) ? 8 : 0);
    const uint32_t sPhiA = (uint32_t)__cvta_generic_to_shared(sPhi);
    const uint32_t sPloA = (uint32_t)__cvta_generic_to_shared(sPlo);
    const uint32_t sWhiA = (uint32_t)__cvta_generic_to_shared(sWhi);
    const uint32_t sWloA = (uint32_t)__cvta_generic_to_shared(sWlo);

    float acc[64];
#pragma unroll
    for (int i = 0; i < 64; i++) acc[i] = 0.f;

#pragma unroll
    for (int kt = 0; kt < 8; kt++) {
        uint32_t ahi[2][4], alo[2][4];
#pragma unroll
        for (int mt = 0; mt < 2; mt++) {
            uint32_t off = (uint32_t)(aoff + mt * 16 * PB + kt * 16) * 2;
            LDSM_X4(ahi[mt][0], ahi[mt][1], ahi[mt][2], ahi[mt][3], sPhiA + off);
            LDSM_X4(alo[mt][0], alo[mt][1], alo[mt][2], alo[mt][3], sPloA + off);
        }
#pragma unroll
        for (int nt = 0; nt < 8; nt++) {
            uint32_t off = (uint32_t)(boff + nt * 8 * PB + kt * 16) * 2;
            uint32_t bh0, bh1, bl0, bl1;
            LDSM_X2(bh0, bh1, sWhiA + off);
            LDSM_X2(bl0, bl1, sWloA + off);
#pragma unroll
            for (int mt = 0; mt < 2; mt++) {
                float* D = acc + (mt * 8 + nt) * 4;
                MMA_BF16(D, ahi[mt][0], ahi[mt][1], ahi[mt][2], ahi[mt][3], bh0, bh1);
                MMA_BF16(D, ahi[mt][0], ahi[mt][1], ahi[mt][2], ahi[mt][3], bl0, bl1);
                MMA_BF16(D, alo[mt][0], alo[mt][1], alo[mt][2], alo[mt][3], bh0, bh1);
            }
        }
    }
    __syncthreads();                                 // P reads done

    // ---- phase 4: tanh -> staging (aliases P) ----
    const int grp = lane >> 2, t4 = lane & 3;
#pragma unroll
    for (int mt = 0; mt < 2; mt++)
#pragma unroll
        for (int nt = 0; nt < 8; nt++) {
            int m = mbase + mt * 16 + grp;
            int n = nbase + nt * 8 + 2 * t4;
            const float* D = acc + (mt * 8 + nt) * 4;
            *(float2*)&sOut[m * POS + n] = make_float2(fast_tanh(D[0]), fast_tanh(D[1]));
            *(float2*)&sOut[(m + 8) * POS + n] = make_float2(fast_tanh(D[2]), fast_tanh(D[3]));
        }
    __syncthreads();

    // ---- phase 5: segment pre-aggregation + vectorized atomics ----
    // thread owns column c4 = t&31, row strip [(t>>5)*16, +16). dst-sorted rows:
    // accumulate runs with equal dst in registers, flush one red per run.
    {
        int c4 = t & 31;
        int r0 = (t >> 5) * 16;
        float4 a = make_float4(0.f, 0.f, 0.f, 0.f);
        int cur = sDst[r0];
#pragma unroll
        for (int j = 0; j < 16; j++) {
            int r = r0 + j;
            int d = sDst[r];                          // uniform across warp
            if (d != cur) {
                float* ptr = C2 + (size_t)cur * BASIS + c4 * 4;
                asm volatile("red.global.add.v4.f32 [%0], {%1,%2,%3,%4};"
                             :: "l"(ptr), "f"(a.x), "f"(a.y), "f"(a.z), "f"(a.w)
                             : "memory");
                a = make_float4(0.f, 0.f, 0.f, 0.f);
                cur = d;
            }
            float4 v = *(float4*)&sOut[r * POS + c4 * 4];
            a.x += v.x; a.y += v.y; a.z += v.z; a.w += v.w;
        }
        float* ptr = C2 + (size_t)cur * BASIS + c4 * 4;
        asm volatile("red.global.add.v4.f32 [%0], {%1,%2,%3,%4};"
                     :: "l"(ptr), "f"(a.x), "f"(a.y), "f"(a.z), "f"(a.w)
                     : "memory");
    }
}

// ---------------- K5: readout + pool ----------------
__global__ __launch_bounds__(256) void k_readout(const float* __restrict__ r1W,
                                                 const float* __restrict__ r1b,
                                                 const float* __restrict__ r2W,
                                                 const float* __restrict__ r2b,
                                                 const int* __restrict__ batch,
                                                 float* __restrict__ out, int sb) {
    extern __shared__ float sm[];
    float* sW1 = sm;                   // [256][128]
    float* sC  = sW1 + 32768;          // [32][132]
    float* sW2 = sC + 32 * 132;        // [4][256]
    float* sB1 = sW2 + 1024;           // [256]
    float* sAcc = sB1 + 256;           // [32][4]
    int*   sBat = (int*)(sAcc + 128);  // [32]
    const float* C = g_C[sb];
    int t = threadIdx.x, n0 = blockIdx.x * 32;

    for (int i = t; i < 8192; i += 256)
        ((float4*)sW1)[i] = ((const float4*)r1W)[i];
    if (t < 256) ((float4*)sW2)[t] = ((const float4*)r2W)[t];
    sB1[t] = r1b[t];
    if (t < 128) sAcc[t] = 0.f;
    if (t < 32)  sBat[t] = batch[n0 + t];
    for (int i = t; i < 32 * 32; i += 256) {
        int n = i >> 5, c4 = i & 31;
        *(float4*)&sC[n * 132 + c4 * 4] = ((const float4*)C)[(size_t)(n0 + n) * 32 + c4];
    }
    __syncthreads();

    int tx = t & 7, ty = t >> 3;
    float acc[4][8];
#pragma unroll
    for (int ii = 0; ii < 4; ii++)
#pragma unroll
        for (int jj = 0; jj < 8; jj++) acc[ii][jj] = 0.f;

#pragma unroll 2
    for (int c = 0; c < 128; c += 4) {
        float4 cv[4], wv[8];
#pragma unroll
        for (int ii = 0; ii < 4; ii++) cv[ii] = *(float4*)&sC[(tx + 8 * ii) * 132 + c];
#pragma unroll
        for (int jj = 0; jj < 8; jj++) wv[jj] = *(float4*)&sW1[(ty * 8 + jj) * 128 + c];
#pragma unroll
        for (int ii = 0; ii < 4; ii++)
#pragma unroll
            for (int jj = 0; jj < 8; jj++) {
                acc[ii][jj] = fmaf(cv[ii].x, wv[jj].x, acc[ii][jj]);
                acc[ii][jj] = fmaf(cv[ii].y, wv[jj].y, acc[ii][jj]);
                acc[ii][jj] = fmaf(cv[ii].z, wv[jj].z, acc[ii][jj]);
                acc[ii][jj] = fmaf(cv[ii].w, wv[jj].w, acc[ii][jj]);
            }
    }
    float po[4][4];
#pragma unroll
    for (int ii = 0; ii < 4; ii++)
#pragma unroll
        for (int o = 0; o < 4; o++) po[ii][o] = (ty == 0) ? r2b[o] : 0.f;
#pragma unroll
    for (int ii = 0; ii < 4; ii++)
#pragma unroll
        for (int jj = 0; jj < 8; jj++) {
            float h = fast_tanh(acc[ii][jj] + sB1[ty * 8 + jj]);
#pragma unroll
            for (int o = 0; o < 4; o++)
                po[ii][o] = fmaf(h, sW2[o * 256 + ty * 8 + jj], po[ii][o]);
        }
#pragma unroll
    for (int ii = 0; ii < 4; ii++)
#pragma unroll
        for (int o = 0; o < 4; o++)
            atomicAdd(&sAcc[(tx + 8 * ii) * 4 + o], po[ii][o]);
    __syncthreads();
    if (t < 128) {
        int n = t >> 2, o = t & 3;
        atomicAdd(&out[(size_t)sBat[n] * 4 + o], sAcc[t]);
    }
}

// ---------------- launch ----------------
extern "C" void kernel_launch(void* const* d_in, const int* in_sizes, int n_in,
                              void* d_out, int out_size) {
    const int*   Z         = (const int*)d_in[0];
    const int*   edge_index= (const int*)d_in[1];
    const float* edge_attr = (const float*)d_in[2];
    const int*   batch     = (const int*)d_in[3];
    const float* embed     = (const float*)d_in[4];
    const float* cfW       = (const float*)d_in[5];
    const float* cfb       = (const float*)d_in[6];
    const float* dfW       = (const float*)d_in[7];
    const float* dfb       = (const float*)d_in[8];
    const float* fcW       = (const float*)d_in[9];
    const float* r1W       = (const float*)d_in[10];
    const float* r1b       = (const float*)d_in[11];
    const float* r2W       = (const float*)d_in[12];
    const float* r2b       = (const float*)d_in[13];
    float* out = (float*)d_out;

    const int smK2 = (128 * 64 + 64 * 68 + 128) * 4 + 64 * 4;             // ~51 KB
    const int smK3 = (16384 + 32 * 132 + 128) * 4;                        // ~83 KB
    const int smK4 = (2 * 128 * PB + 2 * TE * PB) * 2 + 2 * TE * 4;       // ~102.5 KB
    const int smK5 = (32768 + 32 * 132 + 1024 + 256 + 128) * 4 + 32 * 4;  // ~154 KB

    cudaFuncSetAttribute(k_dfeat,   cudaFuncAttributeMaxDynamicSharedMemorySize, smK2);
    cudaFuncSetAttribute(k_node,    cudaFuncAttributeMaxDynamicSharedMemorySize, smK3);
    cudaFuncSetAttribute(k_edge,    cudaFuncAttributeMaxDynamicSharedMemorySize, smK4);
    cudaFuncSetAttribute(k_readout, cudaFuncAttributeMaxDynamicSharedMemorySize, smK5);

    k_zero<<<1, 256>>>(out);
    k_init<<<(N_NODES * 32) / 256, 256>>>(Z, embed);

    // one-time edge sort by dst + W split
    k_clear<<<(N_NODES + 255) / 256, 256>>>();
    k_hist<<<(N_EDGES + 255) / 256, 256>>>(edge_index);
    k_scan<<<1, 1024>>>();
    k_scatter<<<(N_EDGES + 255) / 256, 256>>>(edge_index);
    k_wsplit<<<64, 256>>>(fcW);

    k_dfeat<<<N_EDGES / 64, 256, smK2>>>(edge_attr, dfW, dfb);

    int sb = 0;
    for (int it = 0; it < 3; it++) {
        k_node<<<N_NODES / 32, 256, smK3>>>(cfW, cfb, sb);
        k_edge<<<N_EDGES / TE, 128, smK4>>>(sb ^ 1);
        sb ^= 1;
    }
    k_readout<<<N_NODES / 32, 256, smK5>>>(r1W, r1b, r2W, r2b, batch, out, sb);
}

// round 11
// speedup vs baseline: 1.8125x; 1.4314x over previous
#include <cuda_runtime.h>
#include <cuda_bf16.h>
#include <cstdint>

#define N_NODES   20000
#define N_EDGES   640000
#define BASIS     128
#define NUM_GAUSS 64
#define HIDDEN    256
#define NUM_GRAPHS 256

// ---------------- scratch (device globals) ----------------
__device__ float    g_dfeat[(size_t)N_EDGES * BASIS];  // dst-sorted d_feat
__device__ float    g_C[2][(size_t)N_NODES * BASIS];   // ping-pong node states
__device__ float    g_Cc[(size_t)N_NODES * BASIS];     // per-iter node transform
__device__ uint16_t g_Whi[BASIS * BASIS];              // fcW bf16 hi
__device__ uint16_t g_Wlo[BASIS * BASIS];              // fcW bf16 lo
__device__ int      g_perm[N_EDGES];
__device__ int      g_srcp[N_EDGES];
__device__ int      g_dstp[N_EDGES];
__device__ int      g_cnt[N_NODES];
__device__ int      g_off[N_NODES + 1];
__device__ int      g_cur[N_NODES];

__device__ __forceinline__ float fast_tanh(float x) {        // exact-ish (readout)
    float xc = fminf(fmaxf(x, -9.0f), 9.0f);
    float e  = __expf(2.0f * xc);
    return __fdividef(e - 1.0f, e + 1.0f);
}

__device__ __forceinline__ float tanh_approx(float x) {      // 1 MUFU (edge kernel)
    float y;
    asm("tanh.approx.f32 %0, %1;" : "=f"(y) : "f"(x));
    return y;
}

__device__ __forceinline__ void split_bf16(float x, uint16_t& h, uint16_t& l) {
    __nv_bfloat16 hb = __float2bfloat16_rn(x);
    float hf = __bfloat162float(hb);
    __nv_bfloat16 lb = __float2bfloat16_rn(x - hf);
    h = __bfloat16_as_ushort(hb);
    l = __bfloat16_as_ushort(lb);
}

#define MMA_BF16(D, a0, a1, a2, a3, b0, b1)                                    \
    asm volatile("mma.sync.aligned.m16n8k16.row.col.f32.bf16.bf16.f32 "        \
                 "{%0,%1,%2,%3}, {%4,%5,%6,%7}, {%8,%9}, {%0,%1,%2,%3};"       \
                 : "+f"((D)[0]), "+f"((D)[1]), "+f"((D)[2]), "+f"((D)[3])      \
                 : "r"(a0), "r"(a1), "r"(a2), "r"(a3), "r"(b0), "r"(b1))

#define LDSM_X4(r0, r1, r2, r3, addr)                                          \
    asm volatile("ldmatrix.sync.aligned.m8n8.x4.shared.b16 {%0,%1,%2,%3}, [%4];" \
                 : "=r"(r0), "=r"(r1), "=r"(r2), "=r"(r3) : "r"(addr))

#define LDSM_X2(r0, r1, addr)                                                  \
    asm volatile("ldmatrix.sync.aligned.m8n8.x2.shared.b16 {%0,%1}, [%2];"     \
                 : "=r"(r0), "=r"(r1) : "r"(addr))

// ---------------- K0: zero output ----------------
__global__ void k_zero(float* __restrict__ out) {
    ((float4*)out)[threadIdx.x] = make_float4(0.f, 0.f, 0.f, 0.f);
}

// ---------------- K1: C0 = embed[Z] ----------------
__global__ __launch_bounds__(256) void k_init(const int* __restrict__ Z,
                                              const float* __restrict__ embed) {
    int idx = blockIdx.x * 256 + threadIdx.x;
    int v = idx >> 5, c4 = idx & 31;
    float4 val = ((const float4*)embed)[(size_t)Z[v] * 32 + c4];
    ((float4*)g_C[0])[idx] = val;
}

// ---------------- sort-by-dst pipeline (one-time) ----------------
__global__ __launch_bounds__(256) void k_clear() {
    int i = blockIdx.x * 256 + threadIdx.x;
    if (i < N_NODES) g_cnt[i] = 0;
}

__global__ __launch_bounds__(256) void k_hist(const int* __restrict__ edge_index) {
    int e = blockIdx.x * 256 + threadIdx.x;
    if (e < N_EDGES) atomicAdd(&g_cnt[edge_index[N_EDGES + e]], 1);
}

__global__ __launch_bounds__(1024) void k_scan() {
    __shared__ int sdata[1024];
    int t = threadIdx.x;
    const int PER = 20;
    int base = t * PER;
    int v[PER]; int s = 0;
#pragma unroll
    for (int j = 0; j < PER; j++) {
        int i = base + j;
        v[j] = (i < N_NODES) ? g_cnt[i] : 0;
        s += v[j];
    }
    sdata[t] = s;
    __syncthreads();
    for (int off = 1; off < 1024; off <<= 1) {
        int y = (t >= off) ? sdata[t - off] : 0;
        __syncthreads();
        sdata[t] += y;
        __syncthreads();
    }
    int run = sdata[t] - s;
#pragma unroll
    for (int j = 0; j < PER; j++) {
        int i = base + j;
        if (i < N_NODES) { g_off[i] = run; g_cur[i] = run; run += v[j]; }
    }
    if (t == 1023) g_off[N_NODES] = run;
}

__global__ __launch_bounds__(256) void k_scatter(const int* __restrict__ edge_index) {
    int e = blockIdx.x * 256 + threadIdx.x;
    if (e < N_EDGES) {
        int dst = edge_index[N_EDGES + e];
        int pos = atomicAdd(&g_cur[dst], 1);
        g_perm[pos] = e;
        g_srcp[pos] = edge_index[e];
        g_dstp[pos] = dst;
    }
}

__global__ __launch_bounds__(256) void k_wsplit(const float* __restrict__ fcW) {
    for (int i = blockIdx.x * 256 + threadIdx.x; i < BASIS * BASIS; i += gridDim.x * 256) {
        uint16_t h, l;
        split_bf16(fcW[i], h, l);
        g_Whi[i] = h; g_Wlo[i] = l;
    }
}

// ---------------- K2: d_feat (dst-sorted) = edge_attr[perm] @ dfW.T + dfb ------
__global__ __launch_bounds__(256) void k_dfeat(const float* __restrict__ edge_attr,
                                               const float* __restrict__ dfW,
                                               const float* __restrict__ dfb) {
    extern __shared__ float sm[];
    float* sW = sm;                  // [128][64]
    float* sA = sm + 128 * 64;       // [64][68]
    float* sB = sA + 64 * 68;        // [128]
    int*   sPerm = (int*)(sB + 128); // [64]
    int t = threadIdx.x;
    int e0 = blockIdx.x * 64;

    if (t < 64) sPerm[t] = g_perm[e0 + t];
    __syncthreads();

    for (int i = t; i < 2048; i += 256)
        ((float4*)sW)[i] = ((const float4*)dfW)[i];
    if (t < 128) sB[t] = dfb[t];
    for (int i = t; i < 64 * 16; i += 256) {
        int e = i >> 4, g4 = i & 15;
        float4 v = ((const float4*)edge_attr)[(size_t)sPerm[e] * 16 + g4];
        *(float4*)&sA[e * 68 + g4 * 4] = v;
    }
    __syncthreads();

    int tx = t & 7, ty = t >> 3;
    float acc[8][4];
#pragma unroll
    for (int ii = 0; ii < 8; ii++)
#pragma unroll
        for (int jj = 0; jj < 4; jj++) acc[ii][jj] = 0.f;

#pragma unroll 4
    for (int k = 0; k < 64; k += 4) {
        float4 av[8], wv[4];
#pragma unroll
        for (int ii = 0; ii < 8; ii++) av[ii] = *(float4*)&sA[(tx + 8 * ii) * 68 + k];
#pragma unroll
        for (int jj = 0; jj < 4; jj++) wv[jj] = *(float4*)&sW[(ty * 4 + jj) * 64 + k];
#pragma unroll
        for (int ii = 0; ii < 8; ii++)
#pragma unroll
            for (int jj = 0; jj < 4; jj++) {
                acc[ii][jj] = fmaf(av[ii].x, wv[jj].x, acc[ii][jj]);
                acc[ii][jj] = fmaf(av[ii].y, wv[jj].y, acc[ii][jj]);
                acc[ii][jj] = fmaf(av[ii].z, wv[jj].z, acc[ii][jj]);
                acc[ii][jj] = fmaf(av[ii].w, wv[jj].w, acc[ii][jj]);
            }
    }
    float4 bb = *(float4*)&sB[ty * 4];
#pragma unroll
    for (int ii = 0; ii < 8; ii++) {
        float4 o = make_float4(acc[ii][0] + bb.x, acc[ii][1] + bb.y,
                               acc[ii][2] + bb.z, acc[ii][3] + bb.w);
        ((float4*)g_dfeat)[(size_t)(e0 + tx + 8 * ii) * 32 + ty] = o;
    }
}

// ---------------- K3: Cc = C@cfW.T + cfb ; C2 = C ----------------
__global__ __launch_bounds__(256) void k_node(const float* __restrict__ cfW,
                                              const float* __restrict__ cfb,
                                              int sb) {
    extern __shared__ float sm[];
    float* sW = sm;                  // [128][128]
    float* sC = sm + 16384;          // [32][132]
    float* sBb = sC + 32 * 132;      // [128]
    const float* C = g_C[sb];
    float* C2 = g_C[sb ^ 1];
    int t = threadIdx.x, n0 = blockIdx.x * 32;

    for (int i = t; i < 4096; i += 256)
        ((float4*)sW)[i] = ((const float4*)cfW)[i];
    if (t < 128) sBb[t] = cfb[t];
    for (int i = t; i < 32 * 32; i += 256) {
        int n = i >> 5, c4 = i & 31;
        *(float4*)&sC[n * 132 + c4 * 4] = ((const float4*)C)[(size_t)(n0 + n) * 32 + c4];
    }
    __syncthreads();

    int tx = t & 7, ty = t >> 3;
    float acc[4][4];
#pragma unroll
    for (int ii = 0; ii < 4; ii++)
#pragma unroll
        for (int jj = 0; jj < 4; jj++) acc[ii][jj] = 0.f;

#pragma unroll 4
    for (int k = 0; k < 128; k += 4) {
        float4 cv[4], wv[4];
#pragma unroll
        for (int ii = 0; ii < 4; ii++) cv[ii] = *(float4*)&sC[(tx + 8 * ii) * 132 + k];
#pragma unroll
        for (int jj = 0; jj < 4; jj++) wv[jj] = *(float4*)&sW[(ty * 4 + jj) * 128 + k];
#pragma unroll
        for (int ii = 0; ii < 4; ii++)
#pragma unroll
            for (int jj = 0; jj < 4; jj++) {
                acc[ii][jj] = fmaf(cv[ii].x, wv[jj].x, acc[ii][jj]);
                acc[ii][jj] = fmaf(cv[ii].y, wv[jj].y, acc[ii][jj]);
                acc[ii][jj] = fmaf(cv[ii].z, wv[jj].z, acc[ii][jj]);
                acc[ii][jj] = fmaf(cv[ii].w, wv[jj].w, acc[ii][jj]);
            }
    }
    float4 bb = *(float4*)&sBb[ty * 4];
#pragma unroll
    for (int ii = 0; ii < 4; ii++) {
        float4 o = make_float4(acc[ii][0] + bb.x, acc[ii][1] + bb.y,
                               acc[ii][2] + bb.z, acc[ii][3] + bb.w);
        ((float4*)g_Cc)[(size_t)(n0 + tx + 8 * ii) * 32 + ty] = o;
    }
    for (int i = t; i < 32 * 32; i += 256) {
        int n = i >> 5, c4 = i & 31;
        ((float4*)C2)[(size_t)(n0 + n) * 32 + c4] = *(float4*)&sC[n * 132 + c4 * 4];
    }
}

// ---------------- K4 (hot): m = tanh((Cc[srcp]*d_feat)@fcW.T); C2[dst] += m -----
// TE=64 edges/block, 256 threads (8 warps), ~102.5 KB smem -> 2 blocks/SM.
// Packed bf16x2 split, tanh.approx, dst-sorted run-aggregated atomics.
#define TE  64
#define PB  136   // bf16 row stride
#define POS 132   // f32 staging stride
__global__ __launch_bounds__(256) void k_edge(int db) {
    extern __shared__ char smraw[];
    uint16_t* sWhi = (uint16_t*)smraw;               // [128][136]
    uint16_t* sWlo = sWhi + 128 * PB;                // [128][136]
    uint16_t* sPhi = sWlo + 128 * PB;                // [64][136]
    uint16_t* sPlo = sPhi + TE * PB;                 // [64][136]
    int*      sSrc = (int*)(sPlo + TE * PB);         // [64]
    int*      sDst = sSrc + TE;                      // [64]
    float*    sOut = (float*)sPhi;                   // [64][132], aliases P (hi+lo)
    float* C2 = g_C[db];
    int t = threadIdx.x, e0 = blockIdx.x * TE;

    // ---- phase 1: stage pre-split W; load src/dst ----
    for (int i = t; i < 2048; i += 256) {            // uint4 = 8 bf16
        int n = i >> 4, k8 = i & 15;
        *(uint4*)&sWhi[n * PB + k8 * 8] = ((const uint4*)g_Whi)[i];
        *(uint4*)&sWlo[n * PB + k8 * 8] = ((const uint4*)g_Wlo)[i];
    }
    if (t < TE)          sSrc[t]      = g_srcp[e0 + t];
    else if (t < 2 * TE) sDst[t - TE] = g_dstp[e0 + (t - TE)];
    __syncthreads();

    // ---- phase 2: build & split P = Cc[src] * d_feat (packed bf16x2 cvt) ----
    for (int i = t; i < TE * 32; i += 256) {
        int e = i >> 5, c4 = i & 31;
        float4 d = ((const float4*)g_dfeat)[(size_t)(e0 + e) * 32 + c4];
        float4 c = ((const float4*)g_Cc)[(size_t)sSrc[e] * 32 + c4];
        float p0 = d.x * c.x, p1 = d.y * c.y, p2 = d.z * c.z, p3 = d.w * c.w;
        uint32_t hA, hB;
        asm("cvt.rn.bf16x2.f32 %0, %1, %2;" : "=r"(hA) : "f"(p1), "f"(p0));
        asm("cvt.rn.bf16x2.f32 %0, %1, %2;" : "=r"(hB) : "f"(p3), "f"(p2));
        float r0 = p0 - __uint_as_float(hA << 16);
        float r1 = p1 - __uint_as_float(hA & 0xFFFF0000u);
        float r2 = p2 - __uint_as_float(hB << 16);
        float r3 = p3 - __uint_as_float(hB & 0xFFFF0000u);
        uint32_t lA, lB;
        asm("cvt.rn.bf16x2.f32 %0, %1, %2;" : "=r"(lA) : "f"(r1), "f"(r0));
        asm("cvt.rn.bf16x2.f32 %0, %1, %2;" : "=r"(lB) : "f"(r3), "f"(r2));
        *(uint2*)&sPhi[e * PB + c4 * 4] = make_uint2(hA, hB);
        *(uint2*)&sPlo[e * PB + c4 * 4] = make_uint2(lA, lB);
    }
    __syncthreads();

    // ---- phase 3: bf16-split GEMM  D[64x128] = P @ W^T, 8 warps 2m x 4n ----
    const int lane = t & 31, wid = t >> 5;
    const int mbase = (wid >> 2) * 32;               // {0,32}
    const int nbase = (wid & 3) * 32;                // {0,32,64,96}
    const int aoff = (mbase + (lane & 15)) * PB + ((lane & 16) ? 8 : 0);
    const int boff = (nbase + (lane & 7)) * PB + ((lane & 8) ? 8 : 0);
    const uint32_t sPhiA = (uint32_t)__cvta_generic_to_shared(sPhi);
    const uint32_t sPloA = (uint32_t)__cvta_generic_to_shared(sPlo);
    const uint32_t sWhiA = (uint32_t)__cvta_generic_to_shared(sWhi);
    const uint32_t sWloA = (uint32_t)__cvta_generic_to_shared(sWlo);

    float acc[32];                                   // [mt2][nt4][4]
#pragma unroll
    for (int i = 0; i < 32; i++) acc[i] = 0.f;

#pragma unroll
    for (int kt = 0; kt < 8; kt++) {
        uint32_t ahi[2][4], alo[2][4];
#pragma unroll
        for (int mt = 0; mt < 2; mt++) {
            uint32_t off = (uint32_t)(aoff + mt * 16 * PB + kt * 16) * 2;
            LDSM_X4(ahi[mt][0], ahi[mt][1], ahi[mt][2], ahi[mt][3], sPhiA + off);
            LDSM_X4(alo[mt][0], alo[mt][1], alo[mt][2], alo[mt][3], sPloA + off);
        }
#pragma unroll
        for (int nt = 0; nt < 4; nt++) {
            uint32_t off = (uint32_t)(boff + nt * 8 * PB + kt * 16) * 2;
            uint32_t bh0, bh1, bl0, bl1;
            LDSM_X2(bh0, bh1, sWhiA + off);
            LDSM_X2(bl0, bl1, sWloA + off);
#pragma unroll
            for (int mt = 0; mt < 2; mt++) {
                float* D = acc + (mt * 4 + nt) * 4;
                MMA_BF16(D, ahi[mt][0], ahi[mt][1], ahi[mt][2], ahi[mt][3], bh0, bh1);
                MMA_BF16(D, ahi[mt][0], ahi[mt][1], ahi[mt][2], ahi[mt][3], bl0, bl1);
                MMA_BF16(D, alo[mt][0], alo[mt][1], alo[mt][2], alo[mt][3], bh0, bh1);
            }
        }
    }
    __syncthreads();                                 // P reads done

    // ---- phase 4: tanh.approx -> staging (aliases P) ----
    const int grp = lane >> 2, t4 = lane & 3;
#pragma unroll
    for (int mt = 0; mt < 2; mt++)
#pragma unroll
        for (int nt = 0; nt < 4; nt++) {
            int m = mbase + mt * 16 + grp;
            int n = nbase + nt * 8 + 2 * t4;
            const float* D = acc + (mt * 4 + nt) * 4;
            *(float2*)&sOut[m * POS + n] = make_float2(tanh_approx(D[0]), tanh_approx(D[1]));
            *(float2*)&sOut[(m + 8) * POS + n] = make_float2(tanh_approx(D[2]), tanh_approx(D[3]));
        }
    __syncthreads();

    // ---- phase 5: run-aggregated vectorized atomics (dst-sorted) ----
    {
        int c4 = t & 31;
        int r0 = (t >> 5) * 8;                        // 8 strips x 8 rows
        float4 a = make_float4(0.f, 0.f, 0.f, 0.f);
        int cur = sDst[r0];
#pragma unroll
        for (int j = 0; j < 8; j++) {
            int r = r0 + j;
            int d = sDst[r];                          // uniform across warp
            if (d != cur) {
                float* ptr = C2 + (size_t)cur * BASIS + c4 * 4;
                asm volatile("red.global.add.v4.f32 [%0], {%1,%2,%3,%4};"
                             :: "l"(ptr), "f"(a.x), "f"(a.y), "f"(a.z), "f"(a.w)
                             : "memory");
                a = make_float4(0.f, 0.f, 0.f, 0.f);
                cur = d;
            }
            float4 v = *(float4*)&sOut[r * POS + c4 * 4];
            a.x += v.x; a.y += v.y; a.z += v.z; a.w += v.w;
        }
        float* ptr = C2 + (size_t)cur * BASIS + c4 * 4;
        asm volatile("red.global.add.v4.f32 [%0], {%1,%2,%3,%4};"
                     :: "l"(ptr), "f"(a.x), "f"(a.y), "f"(a.z), "f"(a.w)
                     : "memory");
    }
}

// ---------------- K5: readout + pool ----------------
__global__ __launch_bounds__(256) void k_readout(const float* __restrict__ r1W,
                                                 const float* __restrict__ r1b,
                                                 const float* __restrict__ r2W,
                                                 const float* __restrict__ r2b,
                                                 const int* __restrict__ batch,
                                                 float* __restrict__ out, int sb) {
    extern __shared__ float sm[];
    float* sW1 = sm;                   // [256][128]
    float* sC  = sW1 + 32768;          // [32][132]
    float* sW2 = sC + 32 * 132;        // [4][256]
    float* sB1 = sW2 + 1024;           // [256]
    float* sAcc = sB1 + 256;           // [32][4]
    int*   sBat = (int*)(sAcc + 128);  // [32]
    const float* C = g_C[sb];
    int t = threadIdx.x, n0 = blockIdx.x * 32;

    for (int i = t; i < 8192; i += 256)
        ((float4*)sW1)[i] = ((const float4*)r1W)[i];
    if (t < 256) ((float4*)sW2)[t] = ((const float4*)r2W)[t];
    sB1[t] = r1b[t];
    if (t < 128) sAcc[t] = 0.f;
    if (t < 32)  sBat[t] = batch[n0 + t];
    for (int i = t; i < 32 * 32; i += 256) {
        int n = i >> 5, c4 = i & 31;
        *(float4*)&sC[n * 132 + c4 * 4] = ((const float4*)C)[(size_t)(n0 + n) * 32 + c4];
    }
    __syncthreads();

    int tx = t & 7, ty = t >> 3;
    float acc[4][8];
#pragma unroll
    for (int ii = 0; ii < 4; ii++)
#pragma unroll
        for (int jj = 0; jj < 8; jj++) acc[ii][jj] = 0.f;

#pragma unroll 2
    for (int c = 0; c < 128; c += 4) {
        float4 cv[4], wv[8];
#pragma unroll
        for (int ii = 0; ii < 4; ii++) cv[ii] = *(float4*)&sC[(tx + 8 * ii) * 132 + c];
#pragma unroll
        for (int jj = 0; jj < 8; jj++) wv[jj] = *(float4*)&sW1[(ty * 8 + jj) * 128 + c];
#pragma unroll
        for (int ii = 0; ii < 4; ii++)
#pragma unroll
            for (int jj = 0; jj < 8; jj++) {
                acc[ii][jj] = fmaf(cv[ii].x, wv[jj].x, acc[ii][jj]);
                acc[ii][jj] = fmaf(cv[ii].y, wv[jj].y, acc[ii][jj]);
                acc[ii][jj] = fmaf(cv[ii].z, wv[jj].z, acc[ii][jj]);
                acc[ii][jj] = fmaf(cv[ii].w, wv[jj].w, acc[ii][jj]);
            }
    }
    float po[4][4];
#pragma unroll
    for (int ii = 0; ii < 4; ii++)
#pragma unroll
        for (int o = 0; o < 4; o++) po[ii][o] = (ty == 0) ? r2b[o] : 0.f;
#pragma unroll
    for (int ii = 0; ii < 4; ii++)
#pragma unroll
        for (int jj = 0; jj < 8; jj++) {
            float h = fast_tanh(acc[ii][jj] + sB1[ty * 8 + jj]);
#pragma unroll
            for (int o = 0; o < 4; o++)
                po[ii][o] = fmaf(h, sW2[o * 256 + ty * 8 + jj], po[ii][o]);
        }
#pragma unroll
    for (int ii = 0; ii < 4; ii++)
#pragma unroll
        for (int o = 0; o < 4; o++)
            atomicAdd(&sAcc[(tx + 8 * ii) * 4 + o], po[ii][o]);
    __syncthreads();
    if (t < 128) {
        int n = t >> 2, o = t & 3;
        atomicAdd(&out[(size_t)sBat[n] * 4 + o], sAcc[t]);
    }
}

// ---------------- launch ----------------
extern "C" void kernel_launch(void* const* d_in, const int* in_sizes, int n_in,
                              void* d_out, int out_size) {
    const int*   Z         = (const int*)d_in[0];
    const int*   edge_index= (const int*)d_in[1];
    const float* edge_attr = (const float*)d_in[2];
    const int*   batch     = (const int*)d_in[3];
    const float* embed     = (const float*)d_in[4];
    const float* cfW       = (const float*)d_in[5];
    const float* cfb       = (const float*)d_in[6];
    const float* dfW       = (const float*)d_in[7];
    const float* dfb       = (const float*)d_in[8];
    const float* fcW       = (const float*)d_in[9];
    const float* r1W       = (const float*)d_in[10];
    const float* r1b       = (const float*)d_in[11];
    const float* r2W       = (const float*)d_in[12];
    const float* r2b       = (const float*)d_in[13];
    float* out = (float*)d_out;

    const int smK2 = (128 * 64 + 64 * 68 + 128) * 4 + 64 * 4;             // ~51 KB
    const int smK3 = (16384 + 32 * 132 + 128) * 4;                        // ~83 KB
    const int smK4 = (2 * 128 * PB + 2 * TE * PB) * 2 + 2 * TE * 4;       // ~102.5 KB
    const int smK5 = (32768 + 32 * 132 + 1024 + 256 + 128) * 4 + 32 * 4;  // ~154 KB

    cudaFuncSetAttribute(k_dfeat,   cudaFuncAttributeMaxDynamicSharedMemorySize, smK2);
    cudaFuncSetAttribute(k_node,    cudaFuncAttributeMaxDynamicSharedMemorySize, smK3);
    cudaFuncSetAttribute(k_edge,    cudaFuncAttributeMaxDynamicSharedMemorySize, smK4);
    cudaFuncSetAttribute(k_readout, cudaFuncAttributeMaxDynamicSharedMemorySize, smK5);

    k_zero<<<1, 256>>>(out);
    k_init<<<(N_NODES * 32) / 256, 256>>>(Z, embed);

    // one-time edge sort by dst + W split
    k_clear<<<(N_NODES + 255) / 256, 256>>>();
    k_hist<<<(N_EDGES + 255) / 256, 256>>>(edge_index);
    k_scan<<<1, 1024>>>();
    k_scatter<<<(N_EDGES + 255) / 256, 256>>>(edge_index);
    k_wsplit<<<64, 256>>>(fcW);

    k_dfeat<<<N_EDGES / 64, 256, smK2>>>(edge_attr, dfW, dfb);

    int sb = 0;
    for (int it = 0; it < 3; it++) {
        k_node<<<N_NODES / 32, 256, smK3>>>(cfW, cfb, sb);
        k_edge<<<N_EDGES / TE, 256, smK4>>>(sb ^ 1);
        sb ^= 1;
    }
    k_readout<<<N_NODES / 32, 256, smK5>>>(r1W, r1b, r2W, r2b, batch, out, sb);
}

// round 12
// speedup vs baseline: 2.3121x; 1.2756x over previous
#include <cuda_runtime.h>
#include <cuda_bf16.h>
#include <cuda_fp16.h>
#include <cstdint>

#define N_NODES   20000
#define N_EDGES   640000
#define BASIS     128
#define NUM_GAUSS 64
#define HIDDEN    256
#define NUM_GRAPHS 256

// ---------------- scratch (device globals) ----------------
__device__ float    g_dfeat[(size_t)N_EDGES * BASIS];  // dst-sorted d_feat
__device__ float    g_C[2][(size_t)N_NODES * BASIS];   // ping-pong node states
__device__ float    g_Cc[(size_t)N_NODES * BASIS];     // per-iter node transform
__device__ uint16_t g_Wh[BASIS * BASIS];               // fcW fp16 (single)
__device__ int      g_perm[N_EDGES];
__device__ int      g_srcp[N_EDGES];
__device__ int      g_dstp[N_EDGES];
__device__ int      g_cnt[N_NODES];
__device__ int      g_off[N_NODES + 1];
__device__ int      g_cur[N_NODES];

__device__ __forceinline__ float fast_tanh(float x) {        // readout
    float xc = fminf(fmaxf(x, -9.0f), 9.0f);
    float e  = __expf(2.0f * xc);
    return __fdividef(e - 1.0f, e + 1.0f);
}

__device__ __forceinline__ float tanh_approx(float x) {      // edge kernel
    float y;
    asm("tanh.approx.f32 %0, %1;" : "=f"(y) : "f"(x));
    return y;
}

#define MMA_F16(D, a0, a1, a2, a3, b0, b1)                                     \
    asm volatile("mma.sync.aligned.m16n8k16.row.col.f32.f16.f16.f32 "          \
                 "{%0,%1,%2,%3}, {%4,%5,%6,%7}, {%8,%9}, {%0,%1,%2,%3};"       \
                 : "+f"((D)[0]), "+f"((D)[1]), "+f"((D)[2]), "+f"((D)[3])      \
                 : "r"(a0), "r"(a1), "r"(a2), "r"(a3), "r"(b0), "r"(b1))

#define LDSM_X4(r0, r1, r2, r3, addr)                                          \
    asm volatile("ldmatrix.sync.aligned.m8n8.x4.shared.b16 {%0,%1,%2,%3}, [%4];" \
                 : "=r"(r0), "=r"(r1), "=r"(r2), "=r"(r3) : "r"(addr))

#define LDSM_X2(r0, r1, addr)                                                  \
    asm volatile("ldmatrix.sync.aligned.m8n8.x2.shared.b16 {%0,%1}, [%2];"     \
                 : "=r"(r0), "=r"(r1) : "r"(addr))

// ---------------- K0: zero output ----------------
__global__ void k_zero(float* __restrict__ out) {
    ((float4*)out)[threadIdx.x] = make_float4(0.f, 0.f, 0.f, 0.f);
}

// ---------------- K1: C0 = embed[Z] ----------------
__global__ __launch_bounds__(256) void k_init(const int* __restrict__ Z,
                                              const float* __restrict__ embed) {
    int idx = blockIdx.x * 256 + threadIdx.x;
    int v = idx >> 5, c4 = idx & 31;
    float4 val = ((const float4*)embed)[(size_t)Z[v] * 32 + c4];
    ((float4*)g_C[0])[idx] = val;
}

// ---------------- sort-by-dst pipeline (one-time) ----------------
__global__ __launch_bounds__(256) void k_clear() {
    int i = blockIdx.x * 256 + threadIdx.x;
    if (i < N_NODES) g_cnt[i] = 0;
}

__global__ __launch_bounds__(256) void k_hist(const int* __restrict__ edge_index) {
    int e = blockIdx.x * 256 + threadIdx.x;
    if (e < N_EDGES) atomicAdd(&g_cnt[edge_index[N_EDGES + e]], 1);
}

__global__ __launch_bounds__(1024) void k_scan() {
    __shared__ int sdata[1024];
    int t = threadIdx.x;
    const int PER = 20;
    int base = t * PER;
    int v[PER]; int s = 0;
#pragma unroll
    for (int j = 0; j < PER; j++) {
        int i = base + j;
        v[j] = (i < N_NODES) ? g_cnt[i] : 0;
        s += v[j];
    }
    sdata[t] = s;
    __syncthreads();
    for (int off = 1; off < 1024; off <<= 1) {
        int y = (t >= off) ? sdata[t - off] : 0;
        __syncthreads();
        sdata[t] += y;
        __syncthreads();
    }
    int run = sdata[t] - s;
#pragma unroll
    for (int j = 0; j < PER; j++) {
        int i = base + j;
        if (i < N_NODES) { g_off[i] = run; g_cur[i] = run; run += v[j]; }
    }
    if (t == 1023) g_off[N_NODES] = run;
}

__global__ __launch_bounds__(256) void k_scatter(const int* __restrict__ edge_index) {
    int e = blockIdx.x * 256 + threadIdx.x;
    if (e < N_EDGES) {
        int dst = edge_index[N_EDGES + e];
        int pos = atomicAdd(&g_cur[dst], 1);
        g_perm[pos] = e;
        g_srcp[pos] = edge_index[e];
        g_dstp[pos] = dst;
    }
}

__global__ __launch_bounds__(256) void k_wsplit(const float* __restrict__ fcW) {
    for (int i = blockIdx.x * 256 + threadIdx.x; i < BASIS * BASIS; i += gridDim.x * 256) {
        __half h = __float2half_rn(fcW[i]);
        g_Wh[i] = __half_as_ushort(h);
    }
}

// ---------------- K2: d_feat (dst-sorted) = edge_attr[perm] @ dfW.T + dfb ------
__global__ __launch_bounds__(256) void k_dfeat(const float* __restrict__ edge_attr,
                                               const float* __restrict__ dfW,
                                               const float* __restrict__ dfb) {
    extern __shared__ float sm[];
    float* sW = sm;                  // [128][64]
    float* sA = sm + 128 * 64;       // [64][68]
    float* sB = sA + 64 * 68;        // [128]
    int*   sPerm = (int*)(sB + 128); // [64]
    int t = threadIdx.x;
    int e0 = blockIdx.x * 64;

    if (t < 64) sPerm[t] = g_perm[e0 + t];
    __syncthreads();

    for (int i = t; i < 2048; i += 256)
        ((float4*)sW)[i] = ((const float4*)dfW)[i];
    if (t < 128) sB[t] = dfb[t];
    for (int i = t; i < 64 * 16; i += 256) {
        int e = i >> 4, g4 = i & 15;
        float4 v = ((const float4*)edge_attr)[(size_t)sPerm[e] * 16 + g4];
        *(float4*)&sA[e * 68 + g4 * 4] = v;
    }
    __syncthreads();

    int tx = t & 7, ty = t >> 3;
    float acc[8][4];
#pragma unroll
    for (int ii = 0; ii < 8; ii++)
#pragma unroll
        for (int jj = 0; jj < 4; jj++) acc[ii][jj] = 0.f;

#pragma unroll 4
    for (int k = 0; k < 64; k += 4) {
        float4 av[8], wv[4];
#pragma unroll
        for (int ii = 0; ii < 8; ii++) av[ii] = *(float4*)&sA[(tx + 8 * ii) * 68 + k];
#pragma unroll
        for (int jj = 0; jj < 4; jj++) wv[jj] = *(float4*)&sW[(ty * 4 + jj) * 64 + k];
#pragma unroll
        for (int ii = 0; ii < 8; ii++)
#pragma unroll
            for (int jj = 0; jj < 4; jj++) {
                acc[ii][jj] = fmaf(av[ii].x, wv[jj].x, acc[ii][jj]);
                acc[ii][jj] = fmaf(av[ii].y, wv[jj].y, acc[ii][jj]);
                acc[ii][jj] = fmaf(av[ii].z, wv[jj].z, acc[ii][jj]);
                acc[ii][jj] = fmaf(av[ii].w, wv[jj].w, acc[ii][jj]);
            }
    }
    float4 bb = *(float4*)&sB[ty * 4];
#pragma unroll
    for (int ii = 0; ii < 8; ii++) {
        float4 o = make_float4(acc[ii][0] + bb.x, acc[ii][1] + bb.y,
                               acc[ii][2] + bb.z, acc[ii][3] + bb.w);
        ((float4*)g_dfeat)[(size_t)(e0 + tx + 8 * ii) * 32 + ty] = o;
    }
}

// ---------------- K3: Cc = C@cfW.T + cfb ; C2 = C ----------------
__global__ __launch_bounds__(256) void k_node(const float* __restrict__ cfW,
                                              const float* __restrict__ cfb,
                                              int sb) {
    extern __shared__ float sm[];
    float* sW = sm;                  // [128][128]
    float* sC = sm + 16384;          // [32][132]
    float* sBb = sC + 32 * 132;      // [128]
    const float* C = g_C[sb];
    float* C2 = g_C[sb ^ 1];
    int t = threadIdx.x, n0 = blockIdx.x * 32;

    for (int i = t; i < 4096; i += 256)
        ((float4*)sW)[i] = ((const float4*)cfW)[i];
    if (t < 128) sBb[t] = cfb[t];
    for (int i = t; i < 32 * 32; i += 256) {
        int n = i >> 5, c4 = i & 31;
        *(float4*)&sC[n * 132 + c4 * 4] = ((const float4*)C)[(size_t)(n0 + n) * 32 + c4];
    }
    __syncthreads();

    int tx = t & 7, ty = t >> 3;
    float acc[4][4];
#pragma unroll
    for (int ii = 0; ii < 4; ii++)
#pragma unroll
        for (int jj = 0; jj < 4; jj++) acc[ii][jj] = 0.f;

#pragma unroll 4
    for (int k = 0; k < 128; k += 4) {
        float4 cv[4], wv[4];
#pragma unroll
        for (int ii = 0; ii < 4; ii++) cv[ii] = *(float4*)&sC[(tx + 8 * ii) * 132 + k];
#pragma unroll
        for (int jj = 0; jj < 4; jj++) wv[jj] = *(float4*)&sW[(ty * 4 + jj) * 128 + k];
#pragma unroll
        for (int ii = 0; ii < 4; ii++)
#pragma unroll
            for (int jj = 0; jj < 4; jj++) {
                acc[ii][jj] = fmaf(cv[ii].x, wv[jj].x, acc[ii][jj]);
                acc[ii][jj] = fmaf(cv[ii].y, wv[jj].y, acc[ii][jj]);
                acc[ii][jj] = fmaf(cv[ii].z, wv[jj].z, acc[ii][jj]);
                acc[ii][jj] = fmaf(cv[ii].w, wv[jj].w, acc[ii][jj]);
            }
    }
    float4 bb = *(float4*)&sBb[ty * 4];
#pragma unroll
    for (int ii = 0; ii < 4; ii++) {
        float4 o = make_float4(acc[ii][0] + bb.x, acc[ii][1] + bb.y,
                               acc[ii][2] + bb.z, acc[ii][3] + bb.w);
        ((float4*)g_Cc)[(size_t)(n0 + tx + 8 * ii) * 32 + ty] = o;
    }
    for (int i = t; i < 32 * 32; i += 256) {
        int n = i >> 5, c4 = i & 31;
        ((float4*)C2)[(size_t)(n0 + n) * 32 + c4] = *(float4*)&sC[n * 132 + c4 * 4];
    }
}

// ---------------- K4 (hot): m = tanh((Cc[srcp]*d_feat)@fcW.T); C2[dst] += m -----
// fp16 2-term split on P, single-fp16 W -> 2 MMAs per tile, ~68.5 KB smem,
// 3 blocks/SM. dst-sorted run-aggregated atomics.
#define TE  64
#define PB  136   // fp16 row stride
#define POS 132   // f32 staging stride
__global__ __launch_bounds__(256, 3) void k_edge(int db) {
    extern __shared__ char smraw[];
    uint16_t* sW   = (uint16_t*)smraw;               // [128][136] fp16
    uint16_t* sPhi = sW + 128 * PB;                  // [64][136]
    uint16_t* sPlo = sPhi + TE * PB;                 // [64][136]
    int*      sSrc = (int*)(sPlo + TE * PB);         // [64]
    int*      sDst = sSrc + TE;                      // [64]
    float*    sOut = (float*)sPhi;                   // [64][132], aliases P
    float* C2 = g_C[db];
    int t = threadIdx.x, e0 = blockIdx.x * TE;

    // ---- phase 1: stage fp16 W; load src/dst ----
    for (int i = t; i < 2048; i += 256) {            // uint4 = 8 fp16
        int n = i >> 4, k8 = i & 15;
        *(uint4*)&sW[n * PB + k8 * 8] = ((const uint4*)g_Wh)[i];
    }
    if (t < TE)          sSrc[t]      = g_srcp[e0 + t];
    else if (t < 2 * TE) sDst[t - TE] = g_dstp[e0 + (t - TE)];
    __syncthreads();

    // ---- phase 2: build & split P = Cc[src] * d_feat (fp16 hi/lo) ----
    for (int i = t; i < TE * 32; i += 256) {
        int e = i >> 5, c4 = i & 31;
        float4 d = ((const float4*)g_dfeat)[(size_t)(e0 + e) * 32 + c4];
        float4 c = ((const float4*)g_Cc)[(size_t)sSrc[e] * 32 + c4];
        float p0 = d.x * c.x, p1 = d.y * c.y, p2 = d.z * c.z, p3 = d.w * c.w;
        uint32_t hA, hB;
        asm("cvt.rn.f16x2.f32 %0, %1, %2;" : "=r"(hA) : "f"(p1), "f"(p0));
        asm("cvt.rn.f16x2.f32 %0, %1, %2;" : "=r"(hB) : "f"(p3), "f"(p2));
        __half2 hA2 = *reinterpret_cast<__half2*>(&hA);
        __half2 hB2 = *reinterpret_cast<__half2*>(&hB);
        float r0 = p0 - __low2float(hA2);
        float r1 = p1 - __high2float(hA2);
        float r2 = p2 - __low2float(hB2);
        float r3 = p3 - __high2float(hB2);
        uint32_t lA, lB;
        asm("cvt.rn.f16x2.f32 %0, %1, %2;" : "=r"(lA) : "f"(r1), "f"(r0));
        asm("cvt.rn.f16x2.f32 %0, %1, %2;" : "=r"(lB) : "f"(r3), "f"(r2));
        *(uint2*)&sPhi[e * PB + c4 * 4] = make_uint2(hA, hB);
        *(uint2*)&sPlo[e * PB + c4 * 4] = make_uint2(lA, lB);
    }
    __syncthreads();

    // ---- phase 3: fp16-split GEMM  D[64x128] = P @ W^T, 8 warps 2m x 4n ----
    const int lane = t & 31, wid = t >> 5;
    const int mbase = (wid >> 2) * 32;               // {0,32}
    const int nbase = (wid & 3) * 32;                // {0,32,64,96}
    const int aoff = (mbase + (lane & 15)) * PB + ((lane & 16) ? 8 : 0);
    const int boff = (nbase + (lane & 7)) * PB + ((lane & 8) ? 8 : 0);
    const uint32_t sPhiA = (uint32_t)__cvta_generic_to_shared(sPhi);
    const uint32_t sPloA = (uint32_t)__cvta_generic_to_shared(sPlo);
    const uint32_t sWA   = (uint32_t)__cvta_generic_to_shared(sW);

    float acc[32];                                   // [mt2][nt4][4]
#pragma unroll
    for (int i = 0; i < 32; i++) acc[i] = 0.f;

#pragma unroll
    for (int kt = 0; kt < 8; kt++) {
        uint32_t ahi[2][4], alo[2][4];
#pragma unroll
        for (int mt = 0; mt < 2; mt++) {
            uint32_t off = (uint32_t)(aoff + mt * 16 * PB + kt * 16) * 2;
            LDSM_X4(ahi[mt][0], ahi[mt][1], ahi[mt][2], ahi[mt][3], sPhiA + off);
            LDSM_X4(alo[mt][0], alo[mt][1], alo[mt][2], alo[mt][3], sPloA + off);
        }
#pragma unroll
        for (int nt = 0; nt < 4; nt++) {
            uint32_t off = (uint32_t)(boff + nt * 8 * PB + kt * 16) * 2;
            uint32_t b0, b1;
            LDSM_X2(b0, b1, sWA + off);
#pragma unroll
            for (int mt = 0; mt < 2; mt++) {
                float* D = acc + (mt * 4 + nt) * 4;
                MMA_F16(D, ahi[mt][0], ahi[mt][1], ahi[mt][2], ahi[mt][3], b0, b1);
                MMA_F16(D, alo[mt][0], alo[mt][1], alo[mt][2], alo[mt][3], b0, b1);
            }
        }
    }
    __syncthreads();                                 // P reads done

    // ---- phase 4: tanh.approx -> staging (aliases P) ----
    const int grp = lane >> 2, t4 = lane & 3;
#pragma unroll
    for (int mt = 0; mt < 2; mt++)
#pragma unroll
        for (int nt = 0; nt < 4; nt++) {
            int m = mbase + mt * 16 + grp;
            int n = nbase + nt * 8 + 2 * t4;
            const float* D = acc + (mt * 4 + nt) * 4;
            *(float2*)&sOut[m * POS + n] = make_float2(tanh_approx(D[0]), tanh_approx(D[1]));
            *(float2*)&sOut[(m + 8) * POS + n] = make_float2(tanh_approx(D[2]), tanh_approx(D[3]));
        }
    __syncthreads();

    // ---- phase 5: run-aggregated vectorized atomics (dst-sorted) ----
    {
        int c4 = t & 31;
        int r0 = (t >> 5) * 8;                        // 8 strips x 8 rows
        float4 a = make_float4(0.f, 0.f, 0.f, 0.f);
        int cur = sDst[r0];
#pragma unroll
        for (int j = 0; j < 8; j++) {
            int r = r0 + j;
            int d = sDst[r];                          // uniform across warp
            if (d != cur) {
                float* ptr = C2 + (size_t)cur * BASIS + c4 * 4;
                asm volatile("red.global.add.v4.f32 [%0], {%1,%2,%3,%4};"
                             :: "l"(ptr), "f"(a.x), "f"(a.y), "f"(a.z), "f"(a.w)
                             : "memory");
                a = make_float4(0.f, 0.f, 0.f, 0.f);
                cur = d;
            }
            float4 v = *(float4*)&sOut[r * POS + c4 * 4];
            a.x += v.x; a.y += v.y; a.z += v.z; a.w += v.w;
        }
        float* ptr = C2 + (size_t)cur * BASIS + c4 * 4;
        asm volatile("red.global.add.v4.f32 [%0], {%1,%2,%3,%4};"
                     :: "l"(ptr), "f"(a.x), "f"(a.y), "f"(a.z), "f"(a.w)
                     : "memory");
    }
}

// ---------------- K5: readout + pool ----------------
__global__ __launch_bounds__(256) void k_readout(const float* __restrict__ r1W,
                                                 const float* __restrict__ r1b,
                                                 const float* __restrict__ r2W,
                                                 const float* __restrict__ r2b,
                                                 const int* __restrict__ batch,
                                                 float* __restrict__ out, int sb) {
    extern __shared__ float sm[];
    float* sW1 = sm;                   // [256][128]
    float* sC  = sW1 + 32768;          // [32][132]
    float* sW2 = sC + 32 * 132;        // [4][256]
    float* sB1 = sW2 + 1024;           // [256]
    float* sAcc = sB1 + 256;           // [32][4]
    int*   sBat = (int*)(sAcc + 128);  // [32]
    const float* C = g_C[sb];
    int t = threadIdx.x, n0 = blockIdx.x * 32;

    for (int i = t; i < 8192; i += 256)
        ((float4*)sW1)[i] = ((const float4*)r1W)[i];
    if (t < 256) ((float4*)sW2)[t] = ((const float4*)r2W)[t];
    sB1[t] = r1b[t];
    if (t < 128) sAcc[t] = 0.f;
    if (t < 32)  sBat[t] = batch[n0 + t];
    for (int i = t; i < 32 * 32; i += 256) {
        int n = i >> 5, c4 = i & 31;
        *(float4*)&sC[n * 132 + c4 * 4] = ((const float4*)C)[(size_t)(n0 + n) * 32 + c4];
    }
    __syncthreads();

    int tx = t & 7, ty = t >> 3;
    float acc[4][8];
#pragma unroll
    for (int ii = 0; ii < 4; ii++)
#pragma unroll
        for (int jj = 0; jj < 8; jj++) acc[ii][jj] = 0.f;

#pragma unroll 2
    for (int c = 0; c < 128; c += 4) {
        float4 cv[4], wv[8];
#pragma unroll
        for (int ii = 0; ii < 4; ii++) cv[ii] = *(float4*)&sC[(tx + 8 * ii) * 132 + c];
#pragma unroll
        for (int jj = 0; jj < 8; jj++) wv[jj] = *(float4*)&sW1[(ty * 8 + jj) * 128 + c];
#pragma unroll
        for (int ii = 0; ii < 4; ii++)
#pragma unroll
            for (int jj = 0; jj < 8; jj++) {
                acc[ii][jj] = fmaf(cv[ii].x, wv[jj].x, acc[ii][jj]);
                acc[ii][jj] = fmaf(cv[ii].y, wv[jj].y, acc[ii][jj]);
                acc[ii][jj] = fmaf(cv[ii].z, wv[jj].z, acc[ii][jj]);
                acc[ii][jj] = fmaf(cv[ii].w, wv[jj].w, acc[ii][jj]);
            }
    }
    float po[4][4];
#pragma unroll
    for (int ii = 0; ii < 4; ii++)
#pragma unroll
        for (int o = 0; o < 4; o++) po[ii][o] = (ty == 0) ? r2b[o] : 0.f;
#pragma unroll
    for (int ii = 0; ii < 4; ii++)
#pragma unroll
        for (int jj = 0; jj < 8; jj++) {
            float h = fast_tanh(acc[ii][jj] + sB1[ty * 8 + jj]);
#pragma unroll
            for (int o = 0; o < 4; o++)
                po[ii][o] = fmaf(h, sW2[o * 256 + ty * 8 + jj], po[ii][o]);
        }
#pragma unroll
    for (int ii = 0; ii < 4; ii++)
#pragma unroll
        for (int o = 0; o < 4; o++)
            atomicAdd(&sAcc[(tx + 8 * ii) * 4 + o], po[ii][o]);
    __syncthreads();
    if (t < 128) {
        int n = t >> 2, o = t & 3;
        atomicAdd(&out[(size_t)sBat[n] * 4 + o], sAcc[t]);
    }
}

// ---------------- launch ----------------
extern "C" void kernel_launch(void* const* d_in, const int* in_sizes, int n_in,
                              void* d_out, int out_size) {
    const int*   Z         = (const int*)d_in[0];
    const int*   edge_index= (const int*)d_in[1];
    const float* edge_attr = (const float*)d_in[2];
    const int*   batch     = (const int*)d_in[3];
    const float* embed     = (const float*)d_in[4];
    const float* cfW       = (const float*)d_in[5];
    const float* cfb       = (const float*)d_in[6];
    const float* dfW       = (const float*)d_in[7];
    const float* dfb       = (const float*)d_in[8];
    const float* fcW       = (const float*)d_in[9];
    const float* r1W       = (const float*)d_in[10];
    const float* r1b       = (const float*)d_in[11];
    const float* r2W       = (const float*)d_in[12];
    const float* r2b       = (const float*)d_in[13];
    float* out = (float*)d_out;

    const int smK2 = (128 * 64 + 64 * 68 + 128) * 4 + 64 * 4;             // ~51 KB
    const int smK3 = (16384 + 32 * 132 + 128) * 4;                        // ~83 KB
    const int smK4 = (128 * PB + 2 * TE * PB) * 2 + 2 * TE * 4;           // ~68.5 KB
    const int smK5 = (32768 + 32 * 132 + 1024 + 256 + 128) * 4 + 32 * 4;  // ~154 KB

    cudaFuncSetAttribute(k_dfeat,   cudaFuncAttributeMaxDynamicSharedMemorySize, smK2);
    cudaFuncSetAttribute(k_node,    cudaFuncAttributeMaxDynamicSharedMemorySize, smK3);
    cudaFuncSetAttribute(k_edge,    cudaFuncAttributeMaxDynamicSharedMemorySize, smK4);
    cudaFuncSetAttribute(k_readout, cudaFuncAttributeMaxDynamicSharedMemorySize, smK5);

    k_zero<<<1, 256>>>(out);
    k_init<<<(N_NODES * 32) / 256, 256>>>(Z, embed);

    // one-time edge sort by dst + W fp16 conversion
    k_clear<<<(N_NODES + 255) / 256, 256>>>();
    k_hist<<<(N_EDGES + 255) / 256, 256>>>(edge_index);
    k_scan<<<1, 1024>>>();
    k_scatter<<<(N_EDGES + 255) / 256, 256>>>(edge_index);
    k_wsplit<<<64, 256>>>(fcW);

    k_dfeat<<<N_EDGES / 64, 256, smK2>>>(edge_attr, dfW, dfb);

    int sb = 0;
    for (int it = 0; it < 3; it++) {
        k_node<<<N_NODES / 32, 256, smK3>>>(cfW, cfb, sb);
        k_edge<<<N_EDGES / TE, 256, smK4>>>(sb ^ 1);
        sb ^= 1;
    }
    k_readout<<<N_NODES / 32, 256, smK5>>>(r1W, r1b, r2W, r2b, batch, out, sb);
}

// round 13
// speedup vs baseline: 2.5879x; 1.1193x over previous
#include <cuda_runtime.h>
#include <cuda_bf16.h>
#include <cuda_fp16.h>
#include <cstdint>

#define N_NODES   20000
#define N_EDGES   640000
#define BASIS     128
#define NUM_GAUSS 64
#define HIDDEN    256
#define NUM_GRAPHS 256

// ---------------- scratch (device globals) ----------------
__device__ float    g_dfeat[(size_t)N_EDGES * BASIS];  // dst-sorted d_feat
__device__ float    g_C[2][(size_t)N_NODES * BASIS];   // ping-pong node states
__device__ float    g_Cc[(size_t)N_NODES * BASIS];     // per-iter node transform
__device__ uint16_t g_Wh[BASIS * BASIS];               // fcW fp16
__device__ int      g_perm[N_EDGES];
__device__ int      g_srcp[N_EDGES];
__device__ int      g_dstp[N_EDGES];
__device__ int      g_cnt[N_NODES];
__device__ int      g_off[N_NODES + 1];
__device__ int      g_cur[N_NODES];

__device__ __forceinline__ float fast_tanh(float x) {        // readout
    float xc = fminf(fmaxf(x, -9.0f), 9.0f);
    float e  = __expf(2.0f * xc);
    return __fdividef(e - 1.0f, e + 1.0f);
}

__device__ __forceinline__ float tanh_approx(float x) {      // edge kernel
    float y;
    asm("tanh.approx.f32 %0, %1;" : "=f"(y) : "f"(x));
    return y;
}

#define MMA_F16(D, a0, a1, a2, a3, b0, b1)                                     \
    asm volatile("mma.sync.aligned.m16n8k16.row.col.f32.f16.f16.f32 "          \
                 "{%0,%1,%2,%3}, {%4,%5,%6,%7}, {%8,%9}, {%0,%1,%2,%3};"       \
                 : "+f"((D)[0]), "+f"((D)[1]), "+f"((D)[2]), "+f"((D)[3])      \
                 : "r"(a0), "r"(a1), "r"(a2), "r"(a3), "r"(b0), "r"(b1))

#define LDSM_X4(r0, r1, r2, r3, addr)                                          \
    asm volatile("ldmatrix.sync.aligned.m8n8.x4.shared.b16 {%0,%1,%2,%3}, [%4];" \
                 : "=r"(r0), "=r"(r1), "=r"(r2), "=r"(r3) : "r"(addr))

#define LDSM_X2(r0, r1, addr)                                                  \
    asm volatile("ldmatrix.sync.aligned.m8n8.x2.shared.b16 {%0,%1}, [%2];"     \
                 : "=r"(r0), "=r"(r1) : "r"(addr))

// ---------------- K0: zero output ----------------
__global__ void k_zero(float* __restrict__ out) {
    ((float4*)out)[threadIdx.x] = make_float4(0.f, 0.f, 0.f, 0.f);
}

// ---------------- K1: C0 = embed[Z] ----------------
__global__ __launch_bounds__(256) void k_init(const int* __restrict__ Z,
                                              const float* __restrict__ embed) {
    int idx = blockIdx.x * 256 + threadIdx.x;
    int v = idx >> 5, c4 = idx & 31;
    float4 val = ((const float4*)embed)[(size_t)Z[v] * 32 + c4];
    ((float4*)g_C[0])[idx] = val;
}

// ---------------- sort-by-dst pipeline (one-time) ----------------
__global__ __launch_bounds__(256) void k_clear() {
    int i = blockIdx.x * 256 + threadIdx.x;
    if (i < N_NODES) g_cnt[i] = 0;
}

__global__ __launch_bounds__(256) void k_hist(const int* __restrict__ edge_index) {
    int e = blockIdx.x * 256 + threadIdx.x;
    if (e < N_EDGES) atomicAdd(&g_cnt[edge_index[N_EDGES + e]], 1);
}

__global__ __launch_bounds__(1024) void k_scan() {
    __shared__ int sdata[1024];
    int t = threadIdx.x;
    const int PER = 20;
    int base = t * PER;
    int v[PER]; int s = 0;
#pragma unroll
    for (int j = 0; j < PER; j++) {
        int i = base + j;
        v[j] = (i < N_NODES) ? g_cnt[i] : 0;
        s += v[j];
    }
    sdata[t] = s;
    __syncthreads();
    for (int off = 1; off < 1024; off <<= 1) {
        int y = (t >= off) ? sdata[t - off] : 0;
        __syncthreads();
        sdata[t] += y;
        __syncthreads();
    }
    int run = sdata[t] - s;
#pragma unroll
    for (int j = 0; j < PER; j++) {
        int i = base + j;
        if (i < N_NODES) { g_off[i] = run; g_cur[i] = run; run += v[j]; }
    }
    if (t == 1023) g_off[N_NODES] = run;
}

__global__ __launch_bounds__(256) void k_scatter(const int* __restrict__ edge_index) {
    int e = blockIdx.x * 256 + threadIdx.x;
    if (e < N_EDGES) {
        int dst = edge_index[N_EDGES + e];
        int pos = atomicAdd(&g_cur[dst], 1);
        g_perm[pos] = e;
        g_srcp[pos] = edge_index[e];
        g_dstp[pos] = dst;
    }
}

__global__ __launch_bounds__(256) void k_wsplit(const float* __restrict__ fcW) {
    for (int i = blockIdx.x * 256 + threadIdx.x; i < BASIS * BASIS; i += gridDim.x * 256) {
        __half h = __float2half_rn(fcW[i]);
        g_Wh[i] = __half_as_ushort(h);
    }
}

// ---------------- K2: d_feat (dst-sorted) = edge_attr[perm] @ dfW.T + dfb ------
__global__ __launch_bounds__(256) void k_dfeat(const float* __restrict__ edge_attr,
                                               const float* __restrict__ dfW,
                                               const float* __restrict__ dfb) {
    extern __shared__ float sm[];
    float* sW = sm;                  // [128][64]
    float* sA = sm + 128 * 64;       // [64][68]
    float* sB = sA + 64 * 68;        // [128]
    int*   sPerm = (int*)(sB + 128); // [64]
    int t = threadIdx.x;
    int e0 = blockIdx.x * 64;

    if (t < 64) sPerm[t] = g_perm[e0 + t];
    __syncthreads();

    for (int i = t; i < 2048; i += 256)
        ((float4*)sW)[i] = ((const float4*)dfW)[i];
    if (t < 128) sB[t] = dfb[t];
    for (int i = t; i < 64 * 16; i += 256) {
        int e = i >> 4, g4 = i & 15;
        float4 v = ((const float4*)edge_attr)[(size_t)sPerm[e] * 16 + g4];
        *(float4*)&sA[e * 68 + g4 * 4] = v;
    }
    __syncthreads();

    int tx = t & 7, ty = t >> 3;
    float acc[8][4];
#pragma unroll
    for (int ii = 0; ii < 8; ii++)
#pragma unroll
        for (int jj = 0; jj < 4; jj++) acc[ii][jj] = 0.f;

#pragma unroll 4
    for (int k = 0; k < 64; k += 4) {
        float4 av[8], wv[4];
#pragma unroll
        for (int ii = 0; ii < 8; ii++) av[ii] = *(float4*)&sA[(tx + 8 * ii) * 68 + k];
#pragma unroll
        for (int jj = 0; jj < 4; jj++) wv[jj] = *(float4*)&sW[(ty * 4 + jj) * 64 + k];
#pragma unroll
        for (int ii = 0; ii < 8; ii++)
#pragma unroll
            for (int jj = 0; jj < 4; jj++) {
                acc[ii][jj] = fmaf(av[ii].x, wv[jj].x, acc[ii][jj]);
                acc[ii][jj] = fmaf(av[ii].y, wv[jj].y, acc[ii][jj]);
                acc[ii][jj] = fmaf(av[ii].z, wv[jj].z, acc[ii][jj]);
                acc[ii][jj] = fmaf(av[ii].w, wv[jj].w, acc[ii][jj]);
            }
    }
    float4 bb = *(float4*)&sB[ty * 4];
#pragma unroll
    for (int ii = 0; ii < 8; ii++) {
        float4 o = make_float4(acc[ii][0] + bb.x, acc[ii][1] + bb.y,
                               acc[ii][2] + bb.z, acc[ii][3] + bb.w);
        ((float4*)g_dfeat)[(size_t)(e0 + tx + 8 * ii) * 32 + ty] = o;
    }
}

// ---------------- K3: Cc = C@cfW.T + cfb ; C2 = C ----------------
__global__ __launch_bounds__(256) void k_node(const float* __restrict__ cfW,
                                              const float* __restrict__ cfb,
                                              int sb) {
    extern __shared__ float sm[];
    float* sW = sm;                  // [128][128]
    float* sC = sm + 16384;          // [32][132]
    float* sBb = sC + 32 * 132;      // [128]
    const float* C = g_C[sb];
    float* C2 = g_C[sb ^ 1];
    int t = threadIdx.x, n0 = blockIdx.x * 32;

    for (int i = t; i < 4096; i += 256)
        ((float4*)sW)[i] = ((const float4*)cfW)[i];
    if (t < 128) sBb[t] = cfb[t];
    for (int i = t; i < 32 * 32; i += 256) {
        int n = i >> 5, c4 = i & 31;
        *(float4*)&sC[n * 132 + c4 * 4] = ((const float4*)C)[(size_t)(n0 + n) * 32 + c4];
    }
    __syncthreads();

    int tx = t & 7, ty = t >> 3;
    float acc[4][4];
#pragma unroll
    for (int ii = 0; ii < 4; ii++)
#pragma unroll
        for (int jj = 0; jj < 4; jj++) acc[ii][jj] = 0.f;

#pragma unroll 4
    for (int k = 0; k < 128; k += 4) {
        float4 cv[4], wv[4];
#pragma unroll
        for (int ii = 0; ii < 4; ii++) cv[ii] = *(float4*)&sC[(tx + 8 * ii) * 132 + k];
#pragma unroll
        for (int jj = 0; jj < 4; jj++) wv[jj] = *(float4*)&sW[(ty * 4 + jj) * 128 + k];
#pragma unroll
        for (int ii = 0; ii < 4; ii++)
#pragma unroll
            for (int jj = 0; jj < 4; jj++) {
                acc[ii][jj] = fmaf(cv[ii].x, wv[jj].x, acc[ii][jj]);
                acc[ii][jj] = fmaf(cv[ii].y, wv[jj].y, acc[ii][jj]);
                acc[ii][jj] = fmaf(cv[ii].z, wv[jj].z, acc[ii][jj]);
                acc[ii][jj] = fmaf(cv[ii].w, wv[jj].w, acc[ii][jj]);
            }
    }
    float4 bb = *(float4*)&sBb[ty * 4];
#pragma unroll
    for (int ii = 0; ii < 4; ii++) {
        float4 o = make_float4(acc[ii][0] + bb.x, acc[ii][1] + bb.y,
                               acc[ii][2] + bb.z, acc[ii][3] + bb.w);
        ((float4*)g_Cc)[(size_t)(n0 + tx + 8 * ii) * 32 + ty] = o;
    }
    for (int i = t; i < 32 * 32; i += 256) {
        int n = i >> 5, c4 = i & 31;
        ((float4*)C2)[(size_t)(n0 + n) * 32 + c4] = *(float4*)&sC[n * 132 + c4 * 4];
    }
}

// ---------------- K4 (hot): m = tanh((Cc[srcp]*d_feat)@fcW.T); C2[dst] += m -----
// Single-fp16 P and W -> 1 MMA per tile (64 HMMA/warp). ~51.5 KB smem,
// 4 blocks/SM. Output staged & scattered in two 64-col halves (sOut aliases sPhi).
#define TE  64
#define PB  136   // fp16 row stride
#define POH 68    // f32 staging stride (half of 128 cols + pad)
__global__ __launch_bounds__(256, 4) void k_edge(int db) {
    extern __shared__ char smraw[];
    uint16_t* sW   = (uint16_t*)smraw;               // [128][136] fp16
    uint16_t* sPhi = sW + 128 * PB;                  // [64][136]  fp16
    int*      sSrc = (int*)(sPhi + TE * PB);         // [64]
    int*      sDst = sSrc + TE;                      // [64]
    float*    sOut = (float*)sPhi;                   // [64][68] f32, aliases sPhi
    float* C2 = g_C[db];
    int t = threadIdx.x, e0 = blockIdx.x * TE;

    // ---- phase 1: stage fp16 W; load src/dst ----
    for (int i = t; i < 2048; i += 256) {            // uint4 = 8 fp16
        int n = i >> 4, k8 = i & 15;
        *(uint4*)&sW[n * PB + k8 * 8] = ((const uint4*)g_Wh)[i];
    }
    if (t < TE)          sSrc[t]      = g_srcp[e0 + t];
    else if (t < 2 * TE) sDst[t - TE] = g_dstp[e0 + (t - TE)];
    __syncthreads();

    // ---- phase 2: build P = fp16(Cc[src] * d_feat) ----
    for (int i = t; i < TE * 32; i += 256) {
        int e = i >> 5, c4 = i & 31;
        float4 d = ((const float4*)g_dfeat)[(size_t)(e0 + e) * 32 + c4];
        float4 c = ((const float4*)g_Cc)[(size_t)sSrc[e] * 32 + c4];
        float p0 = d.x * c.x, p1 = d.y * c.y, p2 = d.z * c.z, p3 = d.w * c.w;
        uint32_t hA, hB;
        asm("cvt.rn.f16x2.f32 %0, %1, %2;" : "=r"(hA) : "f"(p1), "f"(p0));
        asm("cvt.rn.f16x2.f32 %0, %1, %2;" : "=r"(hB) : "f"(p3), "f"(p2));
        *(uint2*)&sPhi[e * PB + c4 * 4] = make_uint2(hA, hB);
    }
    __syncthreads();

    // ---- phase 3: fp16 GEMM  D[64x128] = P @ W^T, 8 warps 2m x 4n ----
    const int lane = t & 31, wid = t >> 5;
    const int mbase = (wid >> 2) * 32;               // {0,32}
    const int nbase = (wid & 3) * 32;                // {0,32,64,96}
    const int aoff = (mbase + (lane & 15)) * PB + ((lane & 16) ? 8 : 0);
    const int boff = (nbase + (lane & 7)) * PB + ((lane & 8) ? 8 : 0);
    const uint32_t sPhiA = (uint32_t)__cvta_generic_to_shared(sPhi);
    const uint32_t sWA   = (uint32_t)__cvta_generic_to_shared(sW);

    float acc[32];                                   // [mt2][nt4][4]
#pragma unroll
    for (int i = 0; i < 32; i++) acc[i] = 0.f;

#pragma unroll
    for (int kt = 0; kt < 8; kt++) {
        uint32_t a[2][4];
#pragma unroll
        for (int mt = 0; mt < 2; mt++) {
            uint32_t off = (uint32_t)(aoff + mt * 16 * PB + kt * 16) * 2;
            LDSM_X4(a[mt][0], a[mt][1], a[mt][2], a[mt][3], sPhiA + off);
        }
#pragma unroll
        for (int nt = 0; nt < 4; nt++) {
            uint32_t off = (uint32_t)(boff + nt * 8 * PB + kt * 16) * 2;
            uint32_t b0, b1;
            LDSM_X2(b0, b1, sWA + off);
#pragma unroll
            for (int mt = 0; mt < 2; mt++) {
                float* D = acc + (mt * 4 + nt) * 4;
                MMA_F16(D, a[mt][0], a[mt][1], a[mt][2], a[mt][3], b0, b1);
            }
        }
    }
    __syncthreads();                                 // all sPhi reads done

    // ---- phases 4+5: two column halves; sOut aliases sPhi ----
    const int grp = lane >> 2, t4 = lane & 3;
#pragma unroll
    for (int half = 0; half < 2; half++) {
        if ((nbase >> 6) == half) {                  // warps owning these 64 cols
            int nb = nbase & 63;
#pragma unroll
            for (int mt = 0; mt < 2; mt++)
#pragma unroll
                for (int nt = 0; nt < 4; nt++) {
                    int m = mbase + mt * 16 + grp;
                    int n = nb + nt * 8 + 2 * t4;
                    const float* D = acc + (mt * 4 + nt) * 4;
                    *(float2*)&sOut[m * POH + n] =
                        make_float2(tanh_approx(D[0]), tanh_approx(D[1]));
                    *(float2*)&sOut[(m + 8) * POH + n] =
                        make_float2(tanh_approx(D[2]), tanh_approx(D[3]));
                }
        }
        __syncthreads();
        // run-aggregated scatter for this half (dst-sorted rows)
        {
            int c4 = t & 15;                         // float4 col within half
            int r0 = (t >> 4) * 4;                   // 16 strips x 4 rows
            float4 a4 = make_float4(0.f, 0.f, 0.f, 0.f);
            int cur = sDst[r0];
#pragma unroll
            for (int j = 0; j < 4; j++) {
                int r = r0 + j;
                int d = sDst[r];
                if (d != cur) {
                    float* ptr = C2 + (size_t)cur * BASIS + half * 64 + c4 * 4;
                    asm volatile("red.global.add.v4.f32 [%0], {%1,%2,%3,%4};"
                                 :: "l"(ptr), "f"(a4.x), "f"(a4.y), "f"(a4.z), "f"(a4.w)
                                 : "memory");
                    a4 = make_float4(0.f, 0.f, 0.f, 0.f);
                    cur = d;
                }
                float4 v = *(float4*)&sOut[r * POH + c4 * 4];
                a4.x += v.x; a4.y += v.y; a4.z += v.z; a4.w += v.w;
            }
            float* ptr = C2 + (size_t)cur * BASIS + half * 64 + c4 * 4;
            asm volatile("red.global.add.v4.f32 [%0], {%1,%2,%3,%4};"
                         :: "l"(ptr), "f"(a4.x), "f"(a4.y), "f"(a4.z), "f"(a4.w)
                         : "memory");
        }
        if (half == 0) __syncthreads();              // before overwriting sOut
    }
}

// ---------------- K5: readout + pool ----------------
__global__ __launch_bounds__(256) void k_readout(const float* __restrict__ r1W,
                                                 const float* __restrict__ r1b,
                                                 const float* __restrict__ r2W,
                                                 const float* __restrict__ r2b,
                                                 const int* __restrict__ batch,
                                                 float* __restrict__ out, int sb) {
    extern __shared__ float sm[];
    float* sW1 = sm;                   // [256][128]
    float* sC  = sW1 + 32768;          // [32][132]
    float* sW2 = sC + 32 * 132;        // [4][256]
    float* sB1 = sW2 + 1024;           // [256]
    float* sAcc = sB1 + 256;           // [32][4]
    int*   sBat = (int*)(sAcc + 128);  // [32]
    const float* C = g_C[sb];
    int t = threadIdx.x, n0 = blockIdx.x * 32;

    for (int i = t; i < 8192; i += 256)
        ((float4*)sW1)[i] = ((const float4*)r1W)[i];
    if (t < 256) ((float4*)sW2)[t] = ((const float4*)r2W)[t];
    sB1[t] = r1b[t];
    if (t < 128) sAcc[t] = 0.f;
    if (t < 32)  sBat[t] = batch[n0 + t];
    for (int i = t; i < 32 * 32; i += 256) {
        int n = i >> 5, c4 = i & 31;
        *(float4*)&sC[n * 132 + c4 * 4] = ((const float4*)C)[(size_t)(n0 + n) * 32 + c4];
    }
    __syncthreads();

    int tx = t & 7, ty = t >> 3;
    float acc[4][8];
#pragma unroll
    for (int ii = 0; ii < 4; ii++)
#pragma unroll
        for (int jj = 0; jj < 8; jj++) acc[ii][jj] = 0.f;

#pragma unroll 2
    for (int c = 0; c < 128; c += 4) {
        float4 cv[4], wv[8];
#pragma unroll
        for (int ii = 0; ii < 4; ii++) cv[ii] = *(float4*)&sC[(tx + 8 * ii) * 132 + c];
#pragma unroll
        for (int jj = 0; jj < 8; jj++) wv[jj] = *(float4*)&sW1[(ty * 8 + jj) * 128 + c];
#pragma unroll
        for (int ii = 0; ii < 4; ii++)
#pragma unroll
            for (int jj = 0; jj < 8; jj++) {
                acc[ii][jj] = fmaf(cv[ii].x, wv[jj].x, acc[ii][jj]);
                acc[ii][jj] = fmaf(cv[ii].y, wv[jj].y, acc[ii][jj]);
                acc[ii][jj] = fmaf(cv[ii].z, wv[jj].z, acc[ii][jj]);
                acc[ii][jj] = fmaf(cv[ii].w, wv[jj].w, acc[ii][jj]);
            }
    }
    float po[4][4];
#pragma unroll
    for (int ii = 0; ii < 4; ii++)
#pragma unroll
        for (int o = 0; o < 4; o++) po[ii][o] = (ty == 0) ? r2b[o] : 0.f;
#pragma unroll
    for (int ii = 0; ii < 4; ii++)
#pragma unroll
        for (int jj = 0; jj < 8; jj++) {
            float h = fast_tanh(acc[ii][jj] + sB1[ty * 8 + jj]);
#pragma unroll
            for (int o = 0; o < 4; o++)
                po[ii][o] = fmaf(h, sW2[o * 256 + ty * 8 + jj], po[ii][o]);
        }
#pragma unroll
    for (int ii = 0; ii < 4; ii++)
#pragma unroll
        for (int o = 0; o < 4; o++)
            atomicAdd(&sAcc[(tx + 8 * ii) * 4 + o], po[ii][o]);
    __syncthreads();
    if (t < 128) {
        int n = t >> 2, o = t & 3;
        atomicAdd(&out[(size_t)sBat[n] * 4 + o], sAcc[t]);
    }
}

// ---------------- launch ----------------
extern "C" void kernel_launch(void* const* d_in, const int* in_sizes, int n_in,
                              void* d_out, int out_size) {
    const int*   Z         = (const int*)d_in[0];
    const int*   edge_index= (const int*)d_in[1];
    const float* edge_attr = (const float*)d_in[2];
    const int*   batch     = (const int*)d_in[3];
    const float* embed     = (const float*)d_in[4];
    const float* cfW       = (const float*)d_in[5];
    const float* cfb       = (const float*)d_in[6];
    const float* dfW       = (const float*)d_in[7];
    const float* dfb       = (const float*)d_in[8];
    const float* fcW       = (const float*)d_in[9];
    const float* r1W       = (const float*)d_in[10];
    const float* r1b       = (const float*)d_in[11];
    const float* r2W       = (const float*)d_in[12];
    const float* r2b       = (const float*)d_in[13];
    float* out = (float*)d_out;

    const int smK2 = (128 * 64 + 64 * 68 + 128) * 4 + 64 * 4;             // ~51 KB
    const int smK3 = (16384 + 32 * 132 + 128) * 4;                        // ~83 KB
    const int smK4 = (128 * PB + TE * PB) * 2 + 2 * TE * 4;               // ~51.5 KB
    const int smK5 = (32768 + 32 * 132 + 1024 + 256 + 128) * 4 + 32 * 4;  // ~154 KB

    cudaFuncSetAttribute(k_dfeat,   cudaFuncAttributeMaxDynamicSharedMemorySize, smK2);
    cudaFuncSetAttribute(k_node,    cudaFuncAttributeMaxDynamicSharedMemorySize, smK3);
    cudaFuncSetAttribute(k_edge,    cudaFuncAttributeMaxDynamicSharedMemorySize, smK4);
    cudaFuncSetAttribute(k_readout, cudaFuncAttributeMaxDynamicSharedMemorySize, smK5);

    k_zero<<<1, 256>>>(out);
    k_init<<<(N_NODES * 32) / 256, 256>>>(Z, embed);

    // one-time edge sort by dst + W fp16 conversion
    k_clear<<<(N_NODES + 255) / 256, 256>>>();
    k_hist<<<(N_EDGES + 255) / 256, 256>>>(edge_index);
    k_scan<<<1, 1024>>>();
    k_scatter<<<(N_EDGES + 255) / 256, 256>>>(edge_index);
    k_wsplit<<<64, 256>>>(fcW);

    k_dfeat<<<N_EDGES / 64, 256, smK2>>>(edge_attr, dfW, dfb);

    int sb = 0;
    for (int it = 0; it < 3; it++) {
        k_node<<<N_NODES / 32, 256, smK3>>>(cfW, cfb, sb);
        k_edge<<<N_EDGES / TE, 256, smK4>>>(sb ^ 1);
        sb ^= 1;
    }
    k_readout<<<N_NODES / 32, 256, smK5>>>(r1W, r1b, r2W, r2b, batch, out, sb);
}

// round 14
// speedup vs baseline: 2.6453x; 1.0222x over previous
#include <cuda_runtime.h>
#include <cuda_bf16.h>
#include <cuda_fp16.h>
#include <cstdint>

#define N_NODES   20000
#define N_EDGES   640000
#define BASIS     128
#define NUM_GAUSS 64
#define HIDDEN    256
#define NUM_GRAPHS 256

// ---------------- scratch (device globals) ----------------
__device__ uint16_t g_dfeat16[(size_t)N_EDGES * BASIS]; // dst-sorted d_feat (fp16)
__device__ float    g_C[2][(size_t)N_NODES * BASIS];    // ping-pong node states
__device__ uint16_t g_Cch[(size_t)N_NODES * BASIS];     // per-iter node transform (fp16)
__device__ uint16_t g_Wh[BASIS * BASIS];                // fcW fp16
__device__ int      g_perm[N_EDGES];
__device__ int      g_srcp[N_EDGES];
__device__ int      g_dstp[N_EDGES];
__device__ int      g_cnt[N_NODES];
__device__ int      g_off[N_NODES + 1];
__device__ int      g_cur[N_NODES];

__device__ __forceinline__ float fast_tanh(float x) {        // readout
    float xc = fminf(fmaxf(x, -9.0f), 9.0f);
    float e  = __expf(2.0f * xc);
    return __fdividef(e - 1.0f, e + 1.0f);
}

__device__ __forceinline__ float tanh_approx(float x) {      // edge kernel
    float y;
    asm("tanh.approx.f32 %0, %1;" : "=f"(y) : "f"(x));
    return y;
}

__device__ __forceinline__ uint2 f4_to_h4(float4 o) {
    uint32_t a, b;
    asm("cvt.rn.f16x2.f32 %0, %1, %2;" : "=r"(a) : "f"(o.y), "f"(o.x));
    asm("cvt.rn.f16x2.f32 %0, %1, %2;" : "=r"(b) : "f"(o.w), "f"(o.z));
    return make_uint2(a, b);
}

#define MMA_F16(D, a0, a1, a2, a3, b0, b1)                                     \
    asm volatile("mma.sync.aligned.m16n8k16.row.col.f32.f16.f16.f32 "          \
                 "{%0,%1,%2,%3}, {%4,%5,%6,%7}, {%8,%9}, {%0,%1,%2,%3};"       \
                 : "+f"((D)[0]), "+f"((D)[1]), "+f"((D)[2]), "+f"((D)[3])      \
                 : "r"(a0), "r"(a1), "r"(a2), "r"(a3), "r"(b0), "r"(b1))

#define LDSM_X4(r0, r1, r2, r3, addr)                                          \
    asm volatile("ldmatrix.sync.aligned.m8n8.x4.shared.b16 {%0,%1,%2,%3}, [%4];" \
                 : "=r"(r0), "=r"(r1), "=r"(r2), "=r"(r3) : "r"(addr))

#define LDSM_X2(r0, r1, addr)                                                  \
    asm volatile("ldmatrix.sync.aligned.m8n8.x2.shared.b16 {%0,%1}, [%2];"     \
                 : "=r"(r0), "=r"(r1) : "r"(addr))

// ---------------- K0: zero output ----------------
__global__ void k_zero(float* __restrict__ out) {
    ((float4*)out)[threadIdx.x] = make_float4(0.f, 0.f, 0.f, 0.f);
}

// ---------------- K1: C0 = embed[Z] ----------------
__global__ __launch_bounds__(256) void k_init(const int* __restrict__ Z,
                                              const float* __restrict__ embed) {
    int idx = blockIdx.x * 256 + threadIdx.x;
    int v = idx >> 5, c4 = idx & 31;
    float4 val = ((const float4*)embed)[(size_t)Z[v] * 32 + c4];
    ((float4*)g_C[0])[idx] = val;
}

// ---------------- sort-by-dst pipeline (one-time) ----------------
__global__ __launch_bounds__(256) void k_clear() {
    int i = blockIdx.x * 256 + threadIdx.x;
    if (i < N_NODES) g_cnt[i] = 0;
}

__global__ __launch_bounds__(256) void k_hist(const int* __restrict__ edge_index) {
    int e = blockIdx.x * 256 + threadIdx.x;
    if (e < N_EDGES) atomicAdd(&g_cnt[edge_index[N_EDGES + e]], 1);
}

__global__ __launch_bounds__(1024) void k_scan() {
    __shared__ int sdata[1024];
    int t = threadIdx.x;
    const int PER = 20;
    int base = t * PER;
    int v[PER]; int s = 0;
#pragma unroll
    for (int j = 0; j < PER; j++) {
        int i = base + j;
        v[j] = (i < N_NODES) ? g_cnt[i] : 0;
        s += v[j];
    }
    sdata[t] = s;
    __syncthreads();
    for (int off = 1; off < 1024; off <<= 1) {
        int y = (t >= off) ? sdata[t - off] : 0;
        __syncthreads();
        sdata[t] += y;
        __syncthreads();
    }
    int run = sdata[t] - s;
#pragma unroll
    for (int j = 0; j < PER; j++) {
        int i = base + j;
        if (i < N_NODES) { g_off[i] = run; g_cur[i] = run; run += v[j]; }
    }
    if (t == 1023) g_off[N_NODES] = run;
}

__global__ __launch_bounds__(256) void k_scatter(const int* __restrict__ edge_index) {
    int e = blockIdx.x * 256 + threadIdx.x;
    if (e < N_EDGES) {
        int dst = edge_index[N_EDGES + e];
        int pos = atomicAdd(&g_cur[dst], 1);
        g_perm[pos] = e;
        g_srcp[pos] = edge_index[e];
        g_dstp[pos] = dst;
    }
}

__global__ __launch_bounds__(256) void k_wsplit(const float* __restrict__ fcW) {
    for (int i = blockIdx.x * 256 + threadIdx.x; i < BASIS * BASIS; i += gridDim.x * 256) {
        __half h = __float2half_rn(fcW[i]);
        g_Wh[i] = __half_as_ushort(h);
    }
}

// ---------------- K2: d_feat (dst-sorted, fp16) = edge_attr[perm]@dfW.T + dfb --
__global__ __launch_bounds__(256) void k_dfeat(const float* __restrict__ edge_attr,
                                               const float* __restrict__ dfW,
                                               const float* __restrict__ dfb) {
    extern __shared__ float sm[];
    float* sW = sm;                  // [128][64]
    float* sA = sm + 128 * 64;       // [64][68]
    float* sB = sA + 64 * 68;        // [128]
    int*   sPerm = (int*)(sB + 128); // [64]
    int t = threadIdx.x;
    int e0 = blockIdx.x * 64;

    if (t < 64) sPerm[t] = g_perm[e0 + t];
    __syncthreads();

    for (int i = t; i < 2048; i += 256)
        ((float4*)sW)[i] = ((const float4*)dfW)[i];
    if (t < 128) sB[t] = dfb[t];
    for (int i = t; i < 64 * 16; i += 256) {
        int e = i >> 4, g4 = i & 15;
        float4 v = ((const float4*)edge_attr)[(size_t)sPerm[e] * 16 + g4];
        *(float4*)&sA[e * 68 + g4 * 4] = v;
    }
    __syncthreads();

    int tx = t & 7, ty = t >> 3;
    float acc[8][4];
#pragma unroll
    for (int ii = 0; ii < 8; ii++)
#pragma unroll
        for (int jj = 0; jj < 4; jj++) acc[ii][jj] = 0.f;

#pragma unroll 4
    for (int k = 0; k < 64; k += 4) {
        float4 av[8], wv[4];
#pragma unroll
        for (int ii = 0; ii < 8; ii++) av[ii] = *(float4*)&sA[(tx + 8 * ii) * 68 + k];
#pragma unroll
        for (int jj = 0; jj < 4; jj++) wv[jj] = *(float4*)&sW[(ty * 4 + jj) * 64 + k];
#pragma unroll
        for (int ii = 0; ii < 8; ii++)
#pragma unroll
            for (int jj = 0; jj < 4; jj++) {
                acc[ii][jj] = fmaf(av[ii].x, wv[jj].x, acc[ii][jj]);
                acc[ii][jj] = fmaf(av[ii].y, wv[jj].y, acc[ii][jj]);
                acc[ii][jj] = fmaf(av[ii].z, wv[jj].z, acc[ii][jj]);
                acc[ii][jj] = fmaf(av[ii].w, wv[jj].w, acc[ii][jj]);
            }
    }
    float4 bb = *(float4*)&sB[ty * 4];
#pragma unroll
    for (int ii = 0; ii < 8; ii++) {
        float4 o = make_float4(acc[ii][0] + bb.x, acc[ii][1] + bb.y,
                               acc[ii][2] + bb.z, acc[ii][3] + bb.w);
        ((uint2*)g_dfeat16)[(size_t)(e0 + tx + 8 * ii) * 32 + ty] = f4_to_h4(o);
    }
}

// ---------------- K3: Cc(fp16) = C@cfW.T + cfb ; C2 = C ----------------
__global__ __launch_bounds__(256) void k_node(const float* __restrict__ cfW,
                                              const float* __restrict__ cfb,
                                              int sb) {
    extern __shared__ float sm[];
    float* sW = sm;                  // [128][128]
    float* sC = sm + 16384;          // [32][132]
    float* sBb = sC + 32 * 132;      // [128]
    const float* C = g_C[sb];
    float* C2 = g_C[sb ^ 1];
    int t = threadIdx.x, n0 = blockIdx.x * 32;

    for (int i = t; i < 4096; i += 256)
        ((float4*)sW)[i] = ((const float4*)cfW)[i];
    if (t < 128) sBb[t] = cfb[t];
    for (int i = t; i < 32 * 32; i += 256) {
        int n = i >> 5, c4 = i & 31;
        *(float4*)&sC[n * 132 + c4 * 4] = ((const float4*)C)[(size_t)(n0 + n) * 32 + c4];
    }
    __syncthreads();

    int tx = t & 7, ty = t >> 3;
    float acc[4][4];
#pragma unroll
    for (int ii = 0; ii < 4; ii++)
#pragma unroll
        for (int jj = 0; jj < 4; jj++) acc[ii][jj] = 0.f;

#pragma unroll 4
    for (int k = 0; k < 128; k += 4) {
        float4 cv[4], wv[4];
#pragma unroll
        for (int ii = 0; ii < 4; ii++) cv[ii] = *(float4*)&sC[(tx + 8 * ii) * 132 + k];
#pragma unroll
        for (int jj = 0; jj < 4; jj++) wv[jj] = *(float4*)&sW[(ty * 4 + jj) * 128 + k];
#pragma unroll
        for (int ii = 0; ii < 4; ii++)
#pragma unroll
            for (int jj = 0; jj < 4; jj++) {
                acc[ii][jj] = fmaf(cv[ii].x, wv[jj].x, acc[ii][jj]);
                acc[ii][jj] = fmaf(cv[ii].y, wv[jj].y, acc[ii][jj]);
                acc[ii][jj] = fmaf(cv[ii].z, wv[jj].z, acc[ii][jj]);
                acc[ii][jj] = fmaf(cv[ii].w, wv[jj].w, acc[ii][jj]);
            }
    }
    float4 bb = *(float4*)&sBb[ty * 4];
#pragma unroll
    for (int ii = 0; ii < 4; ii++) {
        float4 o = make_float4(acc[ii][0] + bb.x, acc[ii][1] + bb.y,
                               acc[ii][2] + bb.z, acc[ii][3] + bb.w);
        ((uint2*)g_Cch)[(size_t)(n0 + tx + 8 * ii) * 32 + ty] = f4_to_h4(o);
    }
    for (int i = t; i < 32 * 32; i += 256) {
        int n = i >> 5, c4 = i & 31;
        ((float4*)C2)[(size_t)(n0 + n) * 32 + c4] = *(float4*)&sC[n * 132 + c4 * 4];
    }
}

// ---------------- K4 (hot): m = tanh((Cc[srcp]*d_feat)@fcW.T); C2[dst] += m -----
// All-fp16 operands (dfeat & Cc stored fp16; half2 product). TE=128, 256 thr,
// ~71.7 KB smem -> 3 blocks/SM. Output in two 64-col halves (sOut aliases sP).
#define TE  128
#define PB  136   // fp16 row stride
#define POH 68    // f32 staging stride (64 cols + pad)
__global__ __launch_bounds__(256, 3) void k_edge(int db) {
    extern __shared__ char smraw[];
    uint16_t* sW  = (uint16_t*)smraw;                // [128][136] fp16
    uint16_t* sP  = sW + 128 * PB;                   // [128][136] fp16
    int*      sSrc = (int*)(sP + TE * PB);           // [128]
    int*      sDst = sSrc + TE;                      // [128]
    float*    sOut = (float*)sP;                     // [128][68] f32, aliases sP
    float* C2 = g_C[db];
    int t = threadIdx.x, e0 = blockIdx.x * TE;

    // ---- phase 1: stage fp16 W; load src/dst ----
    for (int i = t; i < 2048; i += 256) {            // uint4 = 8 fp16
        int n = i >> 4, k8 = i & 15;
        *(uint4*)&sW[n * PB + k8 * 8] = ((const uint4*)g_Wh)[i];
    }
    if (t < TE) sSrc[t] = g_srcp[e0 + t];
    else        sDst[t - TE] = g_dstp[e0 + (t - TE)];
    __syncthreads();

    // ---- phase 2: P = h2(Cc[src]) * h2(d_feat)  (all fp16) ----
    for (int i = t; i < TE * 32; i += 256) {
        int e = i >> 5, c4 = i & 31;
        uint2 d2 = ((const uint2*)g_dfeat16)[(size_t)(e0 + e) * 32 + c4];
        uint2 c2 = ((const uint2*)g_Cch)[(size_t)sSrc[e] * 32 + c4];
        __half2 pa = __hmul2(*(__half2*)&d2.x, *(__half2*)&c2.x);
        __half2 pb = __hmul2(*(__half2*)&d2.y, *(__half2*)&c2.y);
        *(uint2*)&sP[e * PB + c4 * 4] =
            make_uint2(*(uint32_t*)&pa, *(uint32_t*)&pb);
    }
    __syncthreads();

    // ---- phase 3: fp16 GEMM  D[128x128] = P @ W^T, 8 warps 4m x 2n (32x64) ----
    const int lane = t & 31, wid = t >> 5;
    const int mbase = (wid >> 1) * 32;               // {0,32,64,96}
    const int nbase = (wid & 1) * 64;                // {0,64}
    const int aoff = (mbase + (lane & 15)) * PB + ((lane & 16) ? 8 : 0);
    const int boff = (nbase + (lane & 7)) * PB + ((lane & 8) ? 8 : 0);
    const uint32_t sPA = (uint32_t)__cvta_generic_to_shared(sP);
    const uint32_t sWA = (uint32_t)__cvta_generic_to_shared(sW);

    float acc[64];                                   // [mt2][nt8][4]
#pragma unroll
    for (int i = 0; i < 64; i++) acc[i] = 0.f;

#pragma unroll
    for (int kt = 0; kt < 8; kt++) {
        uint32_t a[2][4];
#pragma unroll
        for (int mt = 0; mt < 2; mt++) {
            uint32_t off = (uint32_t)(aoff + mt * 16 * PB + kt * 16) * 2;
            LDSM_X4(a[mt][0], a[mt][1], a[mt][2], a[mt][3], sPA + off);
        }
#pragma unroll
        for (int nt = 0; nt < 8; nt++) {
            uint32_t off = (uint32_t)(boff + nt * 8 * PB + kt * 16) * 2;
            uint32_t b0, b1;
            LDSM_X2(b0, b1, sWA + off);
#pragma unroll
            for (int mt = 0; mt < 2; mt++) {
                float* D = acc + (mt * 8 + nt) * 4;
                MMA_F16(D, a[mt][0], a[mt][1], a[mt][2], a[mt][3], b0, b1);
            }
        }
    }
    __syncthreads();                                 // all sP reads done

    // ---- phases 4+5: two column halves; sOut aliases sP ----
    const int grp = lane >> 2, t4 = lane & 3;
#pragma unroll
    for (int half = 0; half < 2; half++) {
        if ((nbase >> 6) == half) {                  // 4 warps own these 64 cols
#pragma unroll
            for (int mt = 0; mt < 2; mt++)
#pragma unroll
                for (int nt = 0; nt < 8; nt++) {
                    int m = mbase + mt * 16 + grp;
                    int n = nt * 8 + 2 * t4;
                    const float* D = acc + (mt * 8 + nt) * 4;
                    *(float2*)&sOut[m * POH + n] =
                        make_float2(tanh_approx(D[0]), tanh_approx(D[1]));
                    *(float2*)&sOut[(m + 8) * POH + n] =
                        make_float2(tanh_approx(D[2]), tanh_approx(D[3]));
                }
        }
        __syncthreads();
        // run-aggregated scatter for this half (dst-sorted rows)
        {
            int c4 = t & 15;                         // float4 col within half
            int r0 = (t >> 4) * 8;                   // 16 strips x 8 rows
            float4 a4 = make_float4(0.f, 0.f, 0.f, 0.f);
            int cur = sDst[r0];
#pragma unroll
            for (int j = 0; j < 8; j++) {
                int r = r0 + j;
                int d = sDst[r];
                if (d != cur) {
                    float* ptr = C2 + (size_t)cur * BASIS + half * 64 + c4 * 4;
                    asm volatile("red.global.add.v4.f32 [%0], {%1,%2,%3,%4};"
                                 :: "l"(ptr), "f"(a4.x), "f"(a4.y), "f"(a4.z), "f"(a4.w)
                                 : "memory");
                    a4 = make_float4(0.f, 0.f, 0.f, 0.f);
                    cur = d;
                }
                float4 v = *(float4*)&sOut[r * POH + c4 * 4];
                a4.x += v.x; a4.y += v.y; a4.z += v.z; a4.w += v.w;
            }
            float* ptr = C2 + (size_t)cur * BASIS + half * 64 + c4 * 4;
            asm volatile("red.global.add.v4.f32 [%0], {%1,%2,%3,%4};"
                         :: "l"(ptr), "f"(a4.x), "f"(a4.y), "f"(a4.z), "f"(a4.w)
                         : "memory");
        }
        if (half == 0) __syncthreads();              // before overwriting sOut
    }
}

// ---------------- K5: readout + pool ----------------
__global__ __launch_bounds__(256) void k_readout(const float* __restrict__ r1W,
                                                 const float* __restrict__ r1b,
                                                 const float* __restrict__ r2W,
                                                 const float* __restrict__ r2b,
                                                 const int* __restrict__ batch,
                                                 float* __restrict__ out, int sb) {
    extern __shared__ float sm[];
    float* sW1 = sm;                   // [256][128]
    float* sC  = sW1 + 32768;          // [32][132]
    float* sW2 = sC + 32 * 132;        // [4][256]
    float* sB1 = sW2 + 1024;           // [256]
    float* sAcc = sB1 + 256;           // [32][4]
    int*   sBat = (int*)(sAcc + 128);  // [32]
    const float* C = g_C[sb];
    int t = threadIdx.x, n0 = blockIdx.x * 32;

    for (int i = t; i < 8192; i += 256)
        ((float4*)sW1)[i] = ((const float4*)r1W)[i];
    if (t < 256) ((float4*)sW2)[t] = ((const float4*)r2W)[t];
    sB1[t] = r1b[t];
    if (t < 128) sAcc[t] = 0.f;
    if (t < 32)  sBat[t] = batch[n0 + t];
    for (int i = t; i < 32 * 32; i += 256) {
        int n = i >> 5, c4 = i & 31;
        *(float4*)&sC[n * 132 + c4 * 4] = ((const float4*)C)[(size_t)(n0 + n) * 32 + c4];
    }
    __syncthreads();

    int tx = t & 7, ty = t >> 3;
    float acc[4][8];
#pragma unroll
    for (int ii = 0; ii < 4; ii++)
#pragma unroll
        for (int jj = 0; jj < 8; jj++) acc[ii][jj] = 0.f;

#pragma unroll 2
    for (int c = 0; c < 128; c += 4) {
        float4 cv[4], wv[8];
#pragma unroll
        for (int ii = 0; ii < 4; ii++) cv[ii] = *(float4*)&sC[(tx + 8 * ii) * 132 + c];
#pragma unroll
        for (int jj = 0; jj < 8; jj++) wv[jj] = *(float4*)&sW1[(ty * 8 + jj) * 128 + c];
#pragma unroll
        for (int ii = 0; ii < 4; ii++)
#pragma unroll
            for (int jj = 0; jj < 8; jj++) {
                acc[ii][jj] = fmaf(cv[ii].x, wv[jj].x, acc[ii][jj]);
                acc[ii][jj] = fmaf(cv[ii].y, wv[jj].y, acc[ii][jj]);
                acc[ii][jj] = fmaf(cv[ii].z, wv[jj].z, acc[ii][jj]);
                acc[ii][jj] = fmaf(cv[ii].w, wv[jj].w, acc[ii][jj]);
            }
    }
    float po[4][4];
#pragma unroll
    for (int ii = 0; ii < 4; ii++)
#pragma unroll
        for (int o = 0; o < 4; o++) po[ii][o] = (ty == 0) ? r2b[o] : 0.f;
#pragma unroll
    for (int ii = 0; ii < 4; ii++)
#pragma unroll
        for (int jj = 0; jj < 8; jj++) {
            float h = fast_tanh(acc[ii][jj] + sB1[ty * 8 + jj]);
#pragma unroll
            for (int o = 0; o < 4; o++)
                po[ii][o] = fmaf(h, sW2[o * 256 + ty * 8 + jj], po[ii][o]);
        }
#pragma unroll
    for (int ii = 0; ii < 4; ii++)
#pragma unroll
        for (int o = 0; o < 4; o++)
            atomicAdd(&sAcc[(tx + 8 * ii) * 4 + o], po[ii][o]);
    __syncthreads();
    if (t < 128) {
        int n = t >> 2, o = t & 3;
        atomicAdd(&out[(size_t)sBat[n] * 4 + o], sAcc[t]);
    }
}

// ---------------- launch ----------------
extern "C" void kernel_launch(void* const* d_in, const int* in_sizes, int n_in,
                              void* d_out, int out_size) {
    const int*   Z         = (const int*)d_in[0];
    const int*   edge_index= (const int*)d_in[1];
    const float* edge_attr = (const float*)d_in[2];
    const int*   batch     = (const int*)d_in[3];
    const float* embed     = (const float*)d_in[4];
    const float* cfW       = (const float*)d_in[5];
    const float* cfb       = (const float*)d_in[6];
    const float* dfW       = (const float*)d_in[7];
    const float* dfb       = (const float*)d_in[8];
    const float* fcW       = (const float*)d_in[9];
    const float* r1W       = (const float*)d_in[10];
    const float* r1b       = (const float*)d_in[11];
    const float* r2W       = (const float*)d_in[12];
    const float* r2b       = (const float*)d_in[13];
    float* out = (float*)d_out;

    const int smK2 = (128 * 64 + 64 * 68 + 128) * 4 + 64 * 4;             // ~51 KB
    const int smK3 = (16384 + 32 * 132 + 128) * 4;                        // ~83 KB
    const int smK4 = (128 * PB + TE * PB) * 2 + 2 * TE * 4;               // ~71.7 KB
    const int smK5 = (32768 + 32 * 132 + 1024 + 256 + 128) * 4 + 32 * 4;  // ~154 KB

    cudaFuncSetAttribute(k_dfeat,   cudaFuncAttributeMaxDynamicSharedMemorySize, smK2);
    cudaFuncSetAttribute(k_node,    cudaFuncAttributeMaxDynamicSharedMemorySize, smK3);
    cudaFuncSetAttribute(k_edge,    cudaFuncAttributeMaxDynamicSharedMemorySize, smK4);
    cudaFuncSetAttribute(k_readout, cudaFuncAttributeMaxDynamicSharedMemorySize, smK5);

    k_zero<<<1, 256>>>(out);
    k_init<<<(N_NODES * 32) / 256, 256>>>(Z, embed);

    // one-time edge sort by dst + W fp16 conversion
    k_clear<<<(N_NODES + 255) / 256, 256>>>();
    k_hist<<<(N_EDGES + 255) / 256, 256>>>(edge_index);
    k_scan<<<1, 1024>>>();
    k_scatter<<<(N_EDGES + 255) / 256, 256>>>(edge_index);
    k_wsplit<<<64, 256>>>(fcW);

    k_dfeat<<<N_EDGES / 64, 256, smK2>>>(edge_attr, dfW, dfb);

    int sb = 0;
    for (int it = 0; it < 3; it++) {
        k_node<<<N_NODES / 32, 256, smK3>>>(cfW, cfb, sb);
        k_edge<<<N_EDGES / TE, 256, smK4>>>(sb ^ 1);
        sb ^= 1;
    }
    k_readout<<<N_NODES / 32, 256, smK5>>>(r1W, r1b, r2W, r2b, batch, out, sb);
}